// round 1
// baseline (speedup 1.0000x reference)
#include <cuda_runtime.h>
#include <math.h>

#define D_MODEL 1024
#define FEED    4096
#define HEADS   16
#define DK      64
#define SEQ     512
#define BATCH   8
#define TOKENS  (BATCH*SEQ)    // 4096
#define BH      (BATCH*HEADS)  // 128

// ---------------- scratch (no allocations allowed) ----------------
__device__ float g_q  [TOKENS*(size_t)D_MODEL];
__device__ float g_k  [TOKENS*(size_t)D_MODEL];
__device__ float g_v  [TOKENS*(size_t)D_MODEL];
__device__ float g_att[(size_t)BH*SEQ*SEQ];       // 128 MB
__device__ float g_ctx[TOKENS*(size_t)D_MODEL];
__device__ float g_x  [TOKENS*(size_t)D_MODEL];
__device__ float g_h  [TOKENS*(size_t)FEED];      // 64 MB
__device__ float g_y  [TOKENS*(size_t)D_MODEL];

// ---------------- generic SGEMM: C = A[M,K] @ W[K,N] + bias, optional ReLU ----
// 128x128 block tile, kTile=16, 256 threads, 8x8 per thread.
template<bool RELU>
__global__ __launch_bounds__(256) void sgemm_bias_kernel(
    const float* __restrict__ A, const float* __restrict__ W,
    const float* __restrict__ bias, float* __restrict__ C,
    int M, int N, int K)
{
    __shared__ float As[16][132];  // A^T tile (padded vs bank conflicts)
    __shared__ float Bs[16][128];  // W tile (float4-aligned rows)

    const int tid = threadIdx.x;
    const int bm  = blockIdx.y * 128;
    const int bn  = blockIdx.x * 128;
    const int tx  = tid & 15;
    const int ty  = tid >> 4;

    float acc[8][8];
#pragma unroll
    for (int i = 0; i < 8; i++)
#pragma unroll
        for (int j = 0; j < 8; j++) acc[i][j] = 0.f;

    for (int k0 = 0; k0 < K; k0 += 16) {
#pragma unroll
        for (int s = tid; s < 512; s += 256) {     // A tile: 128 rows x 16 k
            int r = s >> 2, kq = s & 3;
            float4 v = *reinterpret_cast<const float4*>(
                A + (size_t)(bm + r) * K + k0 + kq * 4);
            As[kq*4+0][r] = v.x;
            As[kq*4+1][r] = v.y;
            As[kq*4+2][r] = v.z;
            As[kq*4+3][r] = v.w;
        }
#pragma unroll
        for (int s = tid; s < 512; s += 256) {     // W tile: 16 k x 128 cols
            int kr = s >> 5, c4 = s & 31;
            *reinterpret_cast<float4*>(&Bs[kr][c4*4]) =
                *reinterpret_cast<const float4*>(
                    W + (size_t)(k0 + kr) * N + bn + c4 * 4);
        }
        __syncthreads();
#pragma unroll
        for (int kk = 0; kk < 16; kk++) {
            float a[8], b[8];
#pragma unroll
            for (int i = 0; i < 4; i++) {
                a[i]   = As[kk][ty*4 + i];
                a[i+4] = As[kk][64 + ty*4 + i];
            }
#pragma unroll
            for (int j = 0; j < 4; j++) {
                b[j]   = Bs[kk][tx*4 + j];
                b[j+4] = Bs[kk][64 + tx*4 + j];
            }
#pragma unroll
            for (int i = 0; i < 8; i++)
#pragma unroll
                for (int j = 0; j < 8; j++)
                    acc[i][j] = fmaf(a[i], b[j], acc[i][j]);
        }
        __syncthreads();
    }
#pragma unroll
    for (int i = 0; i < 8; i++) {
        int row = bm + ((i < 4) ? (ty*4 + i) : (64 + ty*4 + i - 4));
#pragma unroll
        for (int j = 0; j < 8; j++) {
            int col = bn + ((j < 4) ? (tx*4 + j) : (64 + tx*4 + j - 4));
            float v = acc[i][j] + bias[col];
            if (RELU) v = fmaxf(v, 0.f);
            C[(size_t)row * N + col] = v;
        }
    }
}

// ---------------- attention scores: S[bh] = Q_h @ K_h^T * 1/sqrt(dk) ----------
// grid (BH, SEQ/64, SEQ/64), 64x64 tile, full K=64 in smem.
__global__ __launch_bounds__(256) void attn_scores_kernel(
    const float* __restrict__ q, const float* __restrict__ k,
    float* __restrict__ att)
{
    __shared__ float Qs[64][65];
    __shared__ float Ks[64][65];
    const int bh = blockIdx.x;
    const int b  = bh >> 4, h = bh & 15;
    const int q0 = blockIdx.y * 64;
    const int k0 = blockIdx.z * 64;
    const int tid = threadIdx.x;
    const float* qb = q + (size_t)(b*SEQ + q0) * D_MODEL + h*DK;
    const float* kb = k + (size_t)(b*SEQ + k0) * D_MODEL + h*DK;
#pragma unroll
    for (int s = tid; s < 4096; s += 256) {
        int r = s >> 6, c = s & 63;
        Qs[r][c] = qb[(size_t)r * D_MODEL + c];
        Ks[r][c] = kb[(size_t)r * D_MODEL + c];
    }
    __syncthreads();
    const int tx = tid & 15, ty = tid >> 4;
    float acc[4][4] = {};
#pragma unroll 8
    for (int d = 0; d < 64; d++) {
        float a[4], bb[4];
#pragma unroll
        for (int i = 0; i < 4; i++) a[i]  = Qs[ty*4 + i][d];
#pragma unroll
        for (int j = 0; j < 4; j++) bb[j] = Ks[tx*4 + j][d];
#pragma unroll
        for (int i = 0; i < 4; i++)
#pragma unroll
            for (int j = 0; j < 4; j++)
                acc[i][j] = fmaf(a[i], bb[j], acc[i][j]);
    }
    float* outp = att + (size_t)bh * SEQ * SEQ;
#pragma unroll
    for (int i = 0; i < 4; i++)
#pragma unroll
        for (int j = 0; j < 4; j++)
            outp[(size_t)(q0 + ty*4 + i) * SEQ + (k0 + tx*4 + j)] =
                acc[i][j] * 0.125f;   // 1/sqrt(64)
}

// ---------------- softmax over last axis (rows of 512) -----------------------
__global__ __launch_bounds__(256) void softmax_kernel(float* __restrict__ att)
{
    __shared__ float red[8];
    float* p = att + (size_t)blockIdx.x * SEQ;
    const int tid = threadIdx.x;
    float e0 = p[tid], e1 = p[tid + 256];
    float m = fmaxf(e0, e1);
#pragma unroll
    for (int o = 16; o > 0; o >>= 1) m = fmaxf(m, __shfl_xor_sync(~0u, m, o));
    if ((tid & 31) == 0) red[tid >> 5] = m;
    __syncthreads();
    if (tid < 32) {
        float v = (tid < 8) ? red[tid] : -INFINITY;
#pragma unroll
        for (int o = 4; o > 0; o >>= 1) v = fmaxf(v, __shfl_xor_sync(~0u, v, o));
        if (tid == 0) red[0] = v;
    }
    __syncthreads();
    m = red[0];
    __syncthreads();
    e0 = __expf(e0 - m); e1 = __expf(e1 - m);
    float s = e0 + e1;
#pragma unroll
    for (int o = 16; o > 0; o >>= 1) s += __shfl_xor_sync(~0u, s, o);
    if ((tid & 31) == 0) red[tid >> 5] = s;
    __syncthreads();
    if (tid < 32) {
        float v = (tid < 8) ? red[tid] : 0.f;
#pragma unroll
        for (int o = 4; o > 0; o >>= 1) v += __shfl_xor_sync(~0u, v, o);
        if (tid == 0) red[0] = v;
    }
    __syncthreads();
    float inv = 1.f / red[0];
    p[tid]       = e0 * inv;
    p[tid + 256] = e1 * inv;
}

// ---------------- ctx: att[bh] @ V_h, written into head-concat layout --------
// grid (BH, SEQ/64); output 64 q-rows x 64 dk cols per block.
__global__ __launch_bounds__(256) void attn_ctx_kernel(
    const float* __restrict__ att, const float* __restrict__ v,
    float* __restrict__ ctx)
{
    __shared__ float As[64][65];
    __shared__ float Vs[64][65];
    const int bh = blockIdx.x;
    const int b  = bh >> 4, h = bh & 15;
    const int q0 = blockIdx.y * 64;
    const int tid = threadIdx.x;
    const int tx = tid & 15, ty = tid >> 4;
    float acc[4][4] = {};
    const float* arow = att + (size_t)bh * SEQ * SEQ + (size_t)q0 * SEQ;
    for (int kt = 0; kt < SEQ; kt += 64) {
#pragma unroll
        for (int s = tid; s < 4096; s += 256) {
            int r = s >> 6, c = s & 63;
            As[r][c] = arow[(size_t)r * SEQ + kt + c];
            Vs[r][c] = v[(size_t)(b*SEQ + kt + r) * D_MODEL + h*DK + c];
        }
        __syncthreads();
#pragma unroll 8
        for (int kk = 0; kk < 64; kk++) {
            float a[4], bb[4];
#pragma unroll
            for (int i = 0; i < 4; i++) a[i]  = As[ty*4 + i][kk];
#pragma unroll
            for (int j = 0; j < 4; j++) bb[j] = Vs[kk][tx*4 + j];
#pragma unroll
            for (int i = 0; i < 4; i++)
#pragma unroll
                for (int j = 0; j < 4; j++)
                    acc[i][j] = fmaf(a[i], bb[j], acc[i][j]);
        }
        __syncthreads();
    }
#pragma unroll
    for (int i = 0; i < 4; i++)
#pragma unroll
        for (int j = 0; j < 4; j++)
            ctx[(size_t)(b*SEQ + q0 + ty*4 + i) * D_MODEL + h*DK + tx*4 + j] =
                acc[i][j];
}

// ---------------- fused residual-add + LayerNorm (rows of 1024) --------------
__global__ __launch_bounds__(256) void add_ln_kernel(
    const float* __restrict__ a, const float* __restrict__ r,
    const float* __restrict__ g, const float* __restrict__ be,
    float* __restrict__ out)
{
    __shared__ float reds[8], reds2[8];
    __shared__ float s_mean, s_inv;
    const int row = blockIdx.x;
    const int tid = threadIdx.x;
    const float* pa = a + (size_t)row * D_MODEL;
    const float* pr = r + (size_t)row * D_MODEL;
    float vals[4];
    float s = 0.f, s2 = 0.f;
#pragma unroll
    for (int i = 0; i < 4; i++) {
        int c = tid + i * 256;
        float v = pa[c] + pr[c];
        vals[i] = v; s += v; s2 += v * v;
    }
#pragma unroll
    for (int o = 16; o > 0; o >>= 1) {
        s  += __shfl_xor_sync(~0u, s,  o);
        s2 += __shfl_xor_sync(~0u, s2, o);
    }
    if ((tid & 31) == 0) { reds[tid >> 5] = s; reds2[tid >> 5] = s2; }
    __syncthreads();
    if (tid < 32) {
        float v  = (tid < 8) ? reds[tid]  : 0.f;
        float v2 = (tid < 8) ? reds2[tid] : 0.f;
#pragma unroll
        for (int o = 4; o > 0; o >>= 1) {
            v  += __shfl_xor_sync(~0u, v,  o);
            v2 += __shfl_xor_sync(~0u, v2, o);
        }
        if (tid == 0) {
            float mean = v * (1.f / D_MODEL);
            float var  = v2 * (1.f / D_MODEL) - mean * mean;  // biased, = jnp.var
            s_mean = mean;
            s_inv  = rsqrtf(var + 1e-5f);
        }
    }
    __syncthreads();
    float mean = s_mean, inv = s_inv;
#pragma unroll
    for (int i = 0; i < 4; i++) {
        int c = tid + i * 256;
        out[(size_t)row * D_MODEL + c] = (vals[i] - mean) * inv * g[c] + be[c];
    }
}

// ---------------- launch -----------------------------------------------------
extern "C" void kernel_launch(void* const* d_in, const int* in_sizes, int n_in,
                              void* d_out, int out_size)
{
    const float* src = (const float*)d_in[0];
    const float* wq  = (const float*)d_in[1];
    const float* bq  = (const float*)d_in[2];
    const float* wk  = (const float*)d_in[3];
    const float* bk  = (const float*)d_in[4];
    const float* wv  = (const float*)d_in[5];
    const float* bv  = (const float*)d_in[6];
    const float* g1  = (const float*)d_in[7];
    const float* be1 = (const float*)d_in[8];
    const float* w1  = (const float*)d_in[9];
    const float* b1  = (const float*)d_in[10];
    const float* w2  = (const float*)d_in[11];
    const float* b2  = (const float*)d_in[12];
    const float* g2  = (const float*)d_in[13];
    const float* be2 = (const float*)d_in[14];
    float* out = (float*)d_out;

    float *pq, *pk, *pv, *patt, *pctx, *px, *ph, *py;
    cudaGetSymbolAddress((void**)&pq,   g_q);
    cudaGetSymbolAddress((void**)&pk,   g_k);
    cudaGetSymbolAddress((void**)&pv,   g_v);
    cudaGetSymbolAddress((void**)&patt, g_att);
    cudaGetSymbolAddress((void**)&pctx, g_ctx);
    cudaGetSymbolAddress((void**)&px,   g_x);
    cudaGetSymbolAddress((void**)&ph,   g_h);
    cudaGetSymbolAddress((void**)&py,   g_y);

    // QKV projections
    sgemm_bias_kernel<false><<<dim3(D_MODEL/128, TOKENS/128), 256>>>(
        src, wq, bq, pq, TOKENS, D_MODEL, D_MODEL);
    sgemm_bias_kernel<false><<<dim3(D_MODEL/128, TOKENS/128), 256>>>(
        src, wk, bk, pk, TOKENS, D_MODEL, D_MODEL);
    sgemm_bias_kernel<false><<<dim3(D_MODEL/128, TOKENS/128), 256>>>(
        src, wv, bv, pv, TOKENS, D_MODEL, D_MODEL);

    // attention
    attn_scores_kernel<<<dim3(BH, SEQ/64, SEQ/64), 256>>>(pq, pk, patt);
    softmax_kernel<<<BH * SEQ, 256>>>(patt);
    attn_ctx_kernel<<<dim3(BH, SEQ/64), 256>>>(patt, pv, pctx);

    // residual + LN1
    add_ln_kernel<<<TOKENS, 256>>>(pctx, src, g1, be1, px);

    // FFN
    sgemm_bias_kernel<true><<<dim3(FEED/128, TOKENS/128), 256>>>(
        px, w1, b1, ph, TOKENS, FEED, D_MODEL);
    sgemm_bias_kernel<false><<<dim3(D_MODEL/128, TOKENS/128), 256>>>(
        ph, w2, b2, py, TOKENS, D_MODEL, FEED);

    // residual + LN2 -> output
    add_ln_kernel<<<TOKENS, 256>>>(py, px, g2, be2, out);
}

// round 2
// speedup vs baseline: 1.0015x; 1.0015x over previous
#include <cuda_runtime.h>
#include <math.h>

#define D_MODEL 1024
#define FEED    4096
#define HEADS   16
#define DK      64
#define SEQ     512
#define BATCH   8
#define TOKENS  (BATCH*SEQ)    // 4096
#define BH      (BATCH*HEADS)  // 128

// ---------------- scratch (no allocations allowed) ----------------
__device__ float g_q  [TOKENS*(size_t)D_MODEL];
__device__ float g_k  [TOKENS*(size_t)D_MODEL];
__device__ float g_v  [TOKENS*(size_t)D_MODEL];
__device__ float g_att[(size_t)BH*SEQ*SEQ];       // 128 MB
__device__ float g_ctx[TOKENS*(size_t)D_MODEL];
__device__ float g_x  [TOKENS*(size_t)D_MODEL];
__device__ float g_h  [TOKENS*(size_t)FEED];      // 64 MB
__device__ float g_y  [TOKENS*(size_t)D_MODEL];

// ---------------- generic SGEMM: C = A[M,K] @ W[K,N] + bias, optional ReLU ----
// 128x128 block tile, kTile=16, 256 threads, 8x8 per thread.
template<bool RELU>
__global__ __launch_bounds__(256) void sgemm_bias_kernel(
    const float* __restrict__ A, const float* __restrict__ W,
    const float* __restrict__ bias, float* __restrict__ C,
    int M, int N, int K)
{
    __shared__ float As[16][132];  // A^T tile (padded vs bank conflicts)
    __shared__ float Bs[16][128];  // W tile (float4-aligned rows)

    const int tid = threadIdx.x;
    const int bm  = blockIdx.y * 128;
    const int bn  = blockIdx.x * 128;
    const int tx  = tid & 15;
    const int ty  = tid >> 4;

    float acc[8][8];
#pragma unroll
    for (int i = 0; i < 8; i++)
#pragma unroll
        for (int j = 0; j < 8; j++) acc[i][j] = 0.f;

    for (int k0 = 0; k0 < K; k0 += 16) {
#pragma unroll
        for (int s = tid; s < 512; s += 256) {     // A tile: 128 rows x 16 k
            int r = s >> 2, kq = s & 3;
            float4 v = *reinterpret_cast<const float4*>(
                A + (size_t)(bm + r) * K + k0 + kq * 4);
            As[kq*4+0][r] = v.x;
            As[kq*4+1][r] = v.y;
            As[kq*4+2][r] = v.z;
            As[kq*4+3][r] = v.w;
        }
#pragma unroll
        for (int s = tid; s < 512; s += 256) {     // W tile: 16 k x 128 cols
            int kr = s >> 5, c4 = s & 31;
            *reinterpret_cast<float4*>(&Bs[kr][c4*4]) =
                *reinterpret_cast<const float4*>(
                    W + (size_t)(k0 + kr) * N + bn + c4 * 4);
        }
        __syncthreads();
#pragma unroll
        for (int kk = 0; kk < 16; kk++) {
            float a[8], b[8];
#pragma unroll
            for (int i = 0; i < 4; i++) {
                a[i]   = As[kk][ty*4 + i];
                a[i+4] = As[kk][64 + ty*4 + i];
            }
#pragma unroll
            for (int j = 0; j < 4; j++) {
                b[j]   = Bs[kk][tx*4 + j];
                b[j+4] = Bs[kk][64 + tx*4 + j];
            }
#pragma unroll
            for (int i = 0; i < 8; i++)
#pragma unroll
                for (int j = 0; j < 8; j++)
                    acc[i][j] = fmaf(a[i], b[j], acc[i][j]);
        }
        __syncthreads();
    }
#pragma unroll
    for (int i = 0; i < 8; i++) {
        int row = bm + ((i < 4) ? (ty*4 + i) : (64 + ty*4 + i - 4));
#pragma unroll
        for (int j = 0; j < 8; j++) {
            int col = bn + ((j < 4) ? (tx*4 + j) : (64 + tx*4 + j - 4));
            float v = acc[i][j] + bias[col];
            if (RELU) v = fmaxf(v, 0.f);
            C[(size_t)row * N + col] = v;
        }
    }
}

// ---------------- attention scores: S[bh] = Q_h @ K_h^T * 1/sqrt(dk) ----------
// grid (BH, SEQ/64, SEQ/64), 64x64 tile, full K=64 in smem.
__global__ __launch_bounds__(256) void attn_scores_kernel(
    const float* __restrict__ q, const float* __restrict__ k,
    float* __restrict__ att)
{
    __shared__ float Qs[64][65];
    __shared__ float Ks[64][65];
    const int bh = blockIdx.x;
    const int b  = bh >> 4, h = bh & 15;
    const int q0 = blockIdx.y * 64;
    const int k0 = blockIdx.z * 64;
    const int tid = threadIdx.x;
    const float* qb = q + (size_t)(b*SEQ + q0) * D_MODEL + h*DK;
    const float* kb = k + (size_t)(b*SEQ + k0) * D_MODEL + h*DK;
#pragma unroll
    for (int s = tid; s < 4096; s += 256) {
        int r = s >> 6, c = s & 63;
        Qs[r][c] = qb[(size_t)r * D_MODEL + c];
        Ks[r][c] = kb[(size_t)r * D_MODEL + c];
    }
    __syncthreads();
    const int tx = tid & 15, ty = tid >> 4;
    float acc[4][4] = {};
#pragma unroll 8
    for (int d = 0; d < 64; d++) {
        float a[4], bb[4];
#pragma unroll
        for (int i = 0; i < 4; i++) a[i]  = Qs[ty*4 + i][d];
#pragma unroll
        for (int j = 0; j < 4; j++) bb[j] = Ks[tx*4 + j][d];
#pragma unroll
        for (int i = 0; i < 4; i++)
#pragma unroll
            for (int j = 0; j < 4; j++)
                acc[i][j] = fmaf(a[i], bb[j], acc[i][j]);
    }
    float* outp = att + (size_t)bh * SEQ * SEQ;
#pragma unroll
    for (int i = 0; i < 4; i++)
#pragma unroll
        for (int j = 0; j < 4; j++)
            outp[(size_t)(q0 + ty*4 + i) * SEQ + (k0 + tx*4 + j)] =
                acc[i][j] * 0.125f;   // 1/sqrt(64)
}

// ---------------- softmax over last axis (rows of 512) -----------------------
__global__ __launch_bounds__(256) void softmax_kernel(float* __restrict__ att)
{
    __shared__ float red[8];
    float* p = att + (size_t)blockIdx.x * SEQ;
    const int tid = threadIdx.x;
    float e0 = p[tid], e1 = p[tid + 256];
    float m = fmaxf(e0, e1);
#pragma unroll
    for (int o = 16; o > 0; o >>= 1) m = fmaxf(m, __shfl_xor_sync(~0u, m, o));
    if ((tid & 31) == 0) red[tid >> 5] = m;
    __syncthreads();
    if (tid < 32) {
        float v = (tid < 8) ? red[tid] : -INFINITY;
#pragma unroll
        for (int o = 4; o > 0; o >>= 1) v = fmaxf(v, __shfl_xor_sync(~0u, v, o));
        if (tid == 0) red[0] = v;
    }
    __syncthreads();
    m = red[0];
    __syncthreads();
    e0 = __expf(e0 - m); e1 = __expf(e1 - m);
    float s = e0 + e1;
#pragma unroll
    for (int o = 16; o > 0; o >>= 1) s += __shfl_xor_sync(~0u, s, o);
    if ((tid & 31) == 0) red[tid >> 5] = s;
    __syncthreads();
    if (tid < 32) {
        float v = (tid < 8) ? red[tid] : 0.f;
#pragma unroll
        for (int o = 4; o > 0; o >>= 1) v += __shfl_xor_sync(~0u, v, o);
        if (tid == 0) red[0] = v;
    }
    __syncthreads();
    float inv = 1.f / red[0];
    p[tid]       = e0 * inv;
    p[tid + 256] = e1 * inv;
}

// ---------------- ctx: att[bh] @ V_h, written into head-concat layout --------
// grid (BH, SEQ/64); output 64 q-rows x 64 dk cols per block.
__global__ __launch_bounds__(256) void attn_ctx_kernel(
    const float* __restrict__ att, const float* __restrict__ v,
    float* __restrict__ ctx)
{
    __shared__ float As[64][65];
    __shared__ float Vs[64][65];
    const int bh = blockIdx.x;
    const int b  = bh >> 4, h = bh & 15;
    const int q0 = blockIdx.y * 64;
    const int tid = threadIdx.x;
    const int tx = tid & 15, ty = tid >> 4;
    float acc[4][4] = {};
    const float* arow = att + (size_t)bh * SEQ * SEQ + (size_t)q0 * SEQ;
    for (int kt = 0; kt < SEQ; kt += 64) {
#pragma unroll
        for (int s = tid; s < 4096; s += 256) {
            int r = s >> 6, c = s & 63;
            As[r][c] = arow[(size_t)r * SEQ + kt + c];
            Vs[r][c] = v[(size_t)(b*SEQ + kt + r) * D_MODEL + h*DK + c];
        }
        __syncthreads();
#pragma unroll 8
        for (int kk = 0; kk < 64; kk++) {
            float a[4], bb[4];
#pragma unroll
            for (int i = 0; i < 4; i++) a[i]  = As[ty*4 + i][kk];
#pragma unroll
            for (int j = 0; j < 4; j++) bb[j] = Vs[kk][tx*4 + j];
#pragma unroll
            for (int i = 0; i < 4; i++)
#pragma unroll
                for (int j = 0; j < 4; j++)
                    acc[i][j] = fmaf(a[i], bb[j], acc[i][j]);
        }
        __syncthreads();
    }
#pragma unroll
    for (int i = 0; i < 4; i++)
#pragma unroll
        for (int j = 0; j < 4; j++)
            ctx[(size_t)(b*SEQ + q0 + ty*4 + i) * D_MODEL + h*DK + tx*4 + j] =
                acc[i][j];
}

// ---------------- fused residual-add + LayerNorm (rows of 1024) --------------
__global__ __launch_bounds__(256) void add_ln_kernel(
    const float* __restrict__ a, const float* __restrict__ r,
    const float* __restrict__ g, const float* __restrict__ be,
    float* __restrict__ out)
{
    __shared__ float reds[8], reds2[8];
    __shared__ float s_mean, s_inv;
    const int row = blockIdx.x;
    const int tid = threadIdx.x;
    const float* pa = a + (size_t)row * D_MODEL;
    const float* pr = r + (size_t)row * D_MODEL;
    float vals[4];
    float s = 0.f, s2 = 0.f;
#pragma unroll
    for (int i = 0; i < 4; i++) {
        int c = tid + i * 256;
        float v = pa[c] + pr[c];
        vals[i] = v; s += v; s2 += v * v;
    }
#pragma unroll
    for (int o = 16; o > 0; o >>= 1) {
        s  += __shfl_xor_sync(~0u, s,  o);
        s2 += __shfl_xor_sync(~0u, s2, o);
    }
    if ((tid & 31) == 0) { reds[tid >> 5] = s; reds2[tid >> 5] = s2; }
    __syncthreads();
    if (tid < 32) {
        float v  = (tid < 8) ? reds[tid]  : 0.f;
        float v2 = (tid < 8) ? reds2[tid] : 0.f;
#pragma unroll
        for (int o = 4; o > 0; o >>= 1) {
            v  += __shfl_xor_sync(~0u, v,  o);
            v2 += __shfl_xor_sync(~0u, v2, o);
        }
        if (tid == 0) {
            float mean = v * (1.f / D_MODEL);
            float var  = v2 * (1.f / D_MODEL) - mean * mean;  // biased, = jnp.var
            s_mean = mean;
            s_inv  = rsqrtf(var + 1e-5f);
        }
    }
    __syncthreads();
    float mean = s_mean, inv = s_inv;
#pragma unroll
    for (int i = 0; i < 4; i++) {
        int c = tid + i * 256;
        out[(size_t)row * D_MODEL + c] = (vals[i] - mean) * inv * g[c] + be[c];
    }
}

// ---------------- launch -----------------------------------------------------
extern "C" void kernel_launch(void* const* d_in, const int* in_sizes, int n_in,
                              void* d_out, int out_size)
{
    const float* src = (const float*)d_in[0];
    const float* wq  = (const float*)d_in[1];
    const float* bq  = (const float*)d_in[2];
    const float* wk  = (const float*)d_in[3];
    const float* bk  = (const float*)d_in[4];
    const float* wv  = (const float*)d_in[5];
    const float* bv  = (const float*)d_in[6];
    const float* g1  = (const float*)d_in[7];
    const float* be1 = (const float*)d_in[8];
    const float* w1  = (const float*)d_in[9];
    const float* b1  = (const float*)d_in[10];
    const float* w2  = (const float*)d_in[11];
    const float* b2  = (const float*)d_in[12];
    const float* g2  = (const float*)d_in[13];
    const float* be2 = (const float*)d_in[14];
    float* out = (float*)d_out;

    float *pq, *pk, *pv, *patt, *pctx, *px, *ph, *py;
    cudaGetSymbolAddress((void**)&pq,   g_q);
    cudaGetSymbolAddress((void**)&pk,   g_k);
    cudaGetSymbolAddress((void**)&pv,   g_v);
    cudaGetSymbolAddress((void**)&patt, g_att);
    cudaGetSymbolAddress((void**)&pctx, g_ctx);
    cudaGetSymbolAddress((void**)&px,   g_x);
    cudaGetSymbolAddress((void**)&ph,   g_h);
    cudaGetSymbolAddress((void**)&py,   g_y);

    // QKV projections
    sgemm_bias_kernel<false><<<dim3(D_MODEL/128, TOKENS/128), 256>>>(
        src, wq, bq, pq, TOKENS, D_MODEL, D_MODEL);
    sgemm_bias_kernel<false><<<dim3(D_MODEL/128, TOKENS/128), 256>>>(
        src, wk, bk, pk, TOKENS, D_MODEL, D_MODEL);
    sgemm_bias_kernel<false><<<dim3(D_MODEL/128, TOKENS/128), 256>>>(
        src, wv, bv, pv, TOKENS, D_MODEL, D_MODEL);

    // attention
    attn_scores_kernel<<<dim3(BH, SEQ/64, SEQ/64), 256>>>(pq, pk, patt);
    softmax_kernel<<<BH * SEQ, 256>>>(patt);
    attn_ctx_kernel<<<dim3(BH, SEQ/64), 256>>>(patt, pv, pctx);

    // residual + LN1
    add_ln_kernel<<<TOKENS, 256>>>(pctx, src, g1, be1, px);

    // FFN
    sgemm_bias_kernel<true><<<dim3(FEED/128, TOKENS/128), 256>>>(
        px, w1, b1, ph, TOKENS, FEED, D_MODEL);
    sgemm_bias_kernel<false><<<dim3(D_MODEL/128, TOKENS/128), 256>>>(
        ph, w2, b2, py, TOKENS, D_MODEL, FEED);

    // residual + LN2 -> output
    add_ln_kernel<<<TOKENS, 256>>>(py, px, g2, be2, out);
}

// round 4
// speedup vs baseline: 1.2778x; 1.2759x over previous
#include <cuda_runtime.h>
#include <math.h>
#include <stdint.h>

#define D_MODEL 1024
#define FEED    4096
#define HEADS   16
#define DK      64
#define SEQ     512
#define BATCH   8
#define TOKENS  (BATCH*SEQ)    // 4096
#define BH      (BATCH*HEADS)  // 128

// ---------------- scratch (no allocations allowed) ----------------
__device__ float g_q  [TOKENS*(size_t)D_MODEL];
__device__ float g_k  [TOKENS*(size_t)D_MODEL];
__device__ float g_v  [TOKENS*(size_t)D_MODEL];
__device__ float g_att[(size_t)BH*SEQ*SEQ];       // 128 MB
__device__ float g_ctx[TOKENS*(size_t)D_MODEL];
__device__ float g_x  [TOKENS*(size_t)D_MODEL];
__device__ float g_h  [TOKENS*(size_t)FEED];      // 64 MB
__device__ float g_y  [TOKENS*(size_t)D_MODEL];

// ======================= mma.sync TF32 GEMM =======================
// C[M,N] = A[M,K] @ W[K,N] + bias (optional ReLU), 3xTF32 split for fp32 accuracy.
// CTA tile 128x128, BK=32, 8 warps (warp tile 64x32), cp.async 2-stage pipeline.
//
// smem per stage: A tile [128][36] floats (pad 36 -> 144B rows, 16B aligned)
//                 B tile [32][132] floats (pad 132 -> 528B rows, 16B aligned)
#define APAD   36
#define BPAD   132
#define A_BYTES (128*APAD*4)        // 18432
#define B_BYTES (32*BPAD*4)         // 16896
#define STAGE_BYTES (A_BYTES + B_BYTES)  // 35328
#define GEMM_SMEM (2*STAGE_BYTES)        // 70656

#define CP_ASYNC16(dst_u32, src) \
    asm volatile("cp.async.cg.shared.global [%0], [%1], 16;" \
                 :: "r"(dst_u32), "l"(src) : "memory")
#define CP_COMMIT()  asm volatile("cp.async.commit_group;" ::: "memory")
#define CP_WAIT1()   asm volatile("cp.async.wait_group 1;" ::: "memory")
#define CP_WAIT0()   asm volatile("cp.async.wait_group 0;" ::: "memory")

#define MMA_TF32(d, a0,a1,a2,a3, b0,b1) \
    asm volatile("mma.sync.aligned.m16n8k8.row.col.f32.tf32.tf32.f32 " \
        "{%0,%1,%2,%3}, {%4,%5,%6,%7}, {%8,%9}, {%0,%1,%2,%3};" \
        : "+f"((d)[0]), "+f"((d)[1]), "+f"((d)[2]), "+f"((d)[3]) \
        : "r"(a0), "r"(a1), "r"(a2), "r"(a3), "r"(b0), "r"(b1))

__device__ __forceinline__ void tf32_split(float v, uint32_t& hi, uint32_t& lo) {
    uint32_t h = __float_as_uint(v) & 0xffffe000u;
    float lf = v - __uint_as_float(h);
    hi = h;
    lo = __float_as_uint(lf) & 0xffffe000u;
}

template<bool RELU>
__global__ __launch_bounds__(256, 1) void gemm_tc_kernel(
    const float* __restrict__ A, const float* __restrict__ W,
    const float* __restrict__ bias, float* __restrict__ C,
    int M, int N, int K)
{
    extern __shared__ char smem[];
    const uint32_t sbase = (uint32_t)__cvta_generic_to_shared(smem);

    const int tid = threadIdx.x;
    const int wid = tid >> 5;
    const int lane = tid & 31;
    const int gid = lane >> 2;     // 0..7
    const int tig = lane & 3;      // 0..3
    const int wy = wid >> 2;       // 0..1  (warp M position: wy*64)
    const int wx = wid & 3;        // 0..3  (warp N position: wx*32)

    const int bm = blockIdx.y * 128;
    const int bn = blockIdx.x * 128;
    const int nC = K >> 5;

    float acc[4][4][4];
#pragma unroll
    for (int i = 0; i < 4; i++)
#pragma unroll
        for (int j = 0; j < 4; j++)
#pragma unroll
            for (int r = 0; r < 4; r++) acc[i][j][r] = 0.f;

    // fill indices (per thread, 4 chunks for A, 4 for B per stage)
    const int am[4] = { (tid + 0*256) >> 3, (tid + 1*256) >> 3,
                        (tid + 2*256) >> 3, (tid + 3*256) >> 3 };
    const int aq = tid & 7;
    const int bk4[4] = { (tid + 0*256) >> 5, (tid + 1*256) >> 5,
                         (tid + 2*256) >> 5, (tid + 3*256) >> 5 };
    const int bq = tid & 31;

    const float* Ab = A + (size_t)bm * K;

#define ISSUE_STAGE(c) do { \
    const int _s = (c) & 1; \
    const int _k0 = (c) << 5; \
    const uint32_t _sa = sbase + _s * STAGE_BYTES; \
    const uint32_t _sb = _sa + A_BYTES; \
    _Pragma("unroll") \
    for (int _i = 0; _i < 4; _i++) { \
        CP_ASYNC16(_sa + am[_i]*144 + aq*16, \
                   Ab + (size_t)am[_i]*K + _k0 + aq*4); \
    } \
    _Pragma("unroll") \
    for (int _i = 0; _i < 4; _i++) { \
        CP_ASYNC16(_sb + bk4[_i]*528 + bq*16, \
                   W + (size_t)(_k0 + bk4[_i])*N + bn + bq*4); \
    } \
    CP_COMMIT(); \
} while (0)

    ISSUE_STAGE(0);

    for (int c = 0; c < nC; c++) {
        if (c + 1 < nC) { ISSUE_STAGE(c + 1); CP_WAIT1(); }
        else            { CP_WAIT0(); }
        __syncthreads();

        const int s = c & 1;
        const float* pA = reinterpret_cast<const float*>(smem + s * STAGE_BYTES);
        const float* pB = reinterpret_cast<const float*>(smem + s * STAGE_BYTES + A_BYTES);

#pragma unroll
        for (int ks = 0; ks < 4; ks++) {
            const int k0 = ks * 8;
            uint32_t Ah[4][4], Al[4][4];
#pragma unroll
            for (int mt = 0; mt < 4; mt++) {
                const int r0 = wy*64 + mt*16 + gid;
                float v0 = pA[(r0    )*APAD + k0 + tig    ];
                float v1 = pA[(r0 + 8)*APAD + k0 + tig    ];
                float v2 = pA[(r0    )*APAD + k0 + tig + 4];
                float v3 = pA[(r0 + 8)*APAD + k0 + tig + 4];
                tf32_split(v0, Ah[mt][0], Al[mt][0]);
                tf32_split(v1, Ah[mt][1], Al[mt][1]);
                tf32_split(v2, Ah[mt][2], Al[mt][2]);
                tf32_split(v3, Ah[mt][3], Al[mt][3]);
            }
            uint32_t Bh[4][2], Bl[4][2];
#pragma unroll
            for (int nt = 0; nt < 4; nt++) {
                const int nc0 = wx*32 + nt*8 + gid;
                float v0 = pB[(k0 + tig    )*BPAD + nc0];
                float v1 = pB[(k0 + tig + 4)*BPAD + nc0];
                tf32_split(v0, Bh[nt][0], Bl[nt][0]);
                tf32_split(v1, Bh[nt][1], Bl[nt][1]);
            }
#pragma unroll
            for (int mt = 0; mt < 4; mt++) {
#pragma unroll
                for (int nt = 0; nt < 4; nt++) {
                    MMA_TF32(acc[mt][nt], Ah[mt][0], Ah[mt][1], Ah[mt][2], Ah[mt][3],
                             Bh[nt][0], Bh[nt][1]);
                    MMA_TF32(acc[mt][nt], Al[mt][0], Al[mt][1], Al[mt][2], Al[mt][3],
                             Bh[nt][0], Bh[nt][1]);
                    MMA_TF32(acc[mt][nt], Ah[mt][0], Ah[mt][1], Ah[mt][2], Ah[mt][3],
                             Bl[nt][0], Bl[nt][1]);
                }
            }
        }
        __syncthreads();
    }

    // epilogue: direct coalesced-ish float2 stores with bias (+ReLU)
#pragma unroll
    for (int nt = 0; nt < 4; nt++) {
        const int cc = bn + wx*32 + nt*8 + tig*2;
        const float b0 = bias[cc], b1 = bias[cc + 1];
#pragma unroll
        for (int mt = 0; mt < 4; mt++) {
            const int r0 = bm + wy*64 + mt*16 + gid;
            float v0 = acc[mt][nt][0] + b0;
            float v1 = acc[mt][nt][1] + b1;
            float v2 = acc[mt][nt][2] + b0;
            float v3 = acc[mt][nt][3] + b1;
            if (RELU) {
                v0 = fmaxf(v0, 0.f); v1 = fmaxf(v1, 0.f);
                v2 = fmaxf(v2, 0.f); v3 = fmaxf(v3, 0.f);
            }
            *reinterpret_cast<float2*>(C + (size_t)r0 * N + cc)       = make_float2(v0, v1);
            *reinterpret_cast<float2*>(C + (size_t)(r0 + 8) * N + cc) = make_float2(v2, v3);
        }
    }
#undef ISSUE_STAGE
}

// ---------------- attention scores: S[bh] = Q_h @ K_h^T * 1/sqrt(dk) ----------
__global__ __launch_bounds__(256) void attn_scores_kernel(
    const float* __restrict__ q, const float* __restrict__ k,
    float* __restrict__ att)
{
    __shared__ float Qs[64][65];
    __shared__ float Ks[64][65];
    const int bh = blockIdx.x;
    const int b  = bh >> 4, h = bh & 15;
    const int q0 = blockIdx.y * 64;
    const int k0 = blockIdx.z * 64;
    const int tid = threadIdx.x;
    const float* qb = q + (size_t)(b*SEQ + q0) * D_MODEL + h*DK;
    const float* kb = k + (size_t)(b*SEQ + k0) * D_MODEL + h*DK;
#pragma unroll
    for (int s = tid; s < 4096; s += 256) {
        int r = s >> 6, c = s & 63;
        Qs[r][c] = qb[(size_t)r * D_MODEL + c];
        Ks[r][c] = kb[(size_t)r * D_MODEL + c];
    }
    __syncthreads();
    const int tx = tid & 15, ty = tid >> 4;
    float acc[4][4] = {};
#pragma unroll 8
    for (int d = 0; d < 64; d++) {
        float a[4], bb[4];
#pragma unroll
        for (int i = 0; i < 4; i++) a[i]  = Qs[ty*4 + i][d];
#pragma unroll
        for (int j = 0; j < 4; j++) bb[j] = Ks[tx*4 + j][d];
#pragma unroll
        for (int i = 0; i < 4; i++)
#pragma unroll
            for (int j = 0; j < 4; j++)
                acc[i][j] = fmaf(a[i], bb[j], acc[i][j]);
    }
    float* outp = att + (size_t)bh * SEQ * SEQ;
#pragma unroll
    for (int i = 0; i < 4; i++)
#pragma unroll
        for (int j = 0; j < 4; j++)
            outp[(size_t)(q0 + ty*4 + i) * SEQ + (k0 + tx*4 + j)] =
                acc[i][j] * 0.125f;   // 1/sqrt(64)
}

// ---------------- softmax over last axis (rows of 512) -----------------------
__global__ __launch_bounds__(256) void softmax_kernel(float* __restrict__ att)
{
    __shared__ float red[8];
    float* p = att + (size_t)blockIdx.x * SEQ;
    const int tid = threadIdx.x;
    float e0 = p[tid], e1 = p[tid + 256];
    float m = fmaxf(e0, e1);
#pragma unroll
    for (int o = 16; o > 0; o >>= 1) m = fmaxf(m, __shfl_xor_sync(~0u, m, o));
    if ((tid & 31) == 0) red[tid >> 5] = m;
    __syncthreads();
    if (tid < 32) {
        float v = (tid < 8) ? red[tid] : -INFINITY;
#pragma unroll
        for (int o = 4; o > 0; o >>= 1) v = fmaxf(v, __shfl_xor_sync(~0u, v, o));
        if (tid == 0) red[0] = v;
    }
    __syncthreads();
    m = red[0];
    __syncthreads();
    e0 = __expf(e0 - m); e1 = __expf(e1 - m);
    float s = e0 + e1;
#pragma unroll
    for (int o = 16; o > 0; o >>= 1) s += __shfl_xor_sync(~0u, s, o);
    if ((tid & 31) == 0) red[tid >> 5] = s;
    __syncthreads();
    if (tid < 32) {
        float v = (tid < 8) ? red[tid] : 0.f;
#pragma unroll
        for (int o = 4; o > 0; o >>= 1) v += __shfl_xor_sync(~0u, v, o);
        if (tid == 0) red[0] = v;
    }
    __syncthreads();
    float inv = 1.f / red[0];
    p[tid]       = e0 * inv;
    p[tid + 256] = e1 * inv;
}

// ---------------- ctx: att[bh] @ V_h, written into head-concat layout --------
__global__ __launch_bounds__(256) void attn_ctx_kernel(
    const float* __restrict__ att, const float* __restrict__ v,
    float* __restrict__ ctx)
{
    __shared__ float As[64][65];
    __shared__ float Vs[64][65];
    const int bh = blockIdx.x;
    const int b  = bh >> 4, h = bh & 15;
    const int q0 = blockIdx.y * 64;
    const int tid = threadIdx.x;
    const int tx = tid & 15, ty = tid >> 4;
    float acc[4][4] = {};
    const float* arow = att + (size_t)bh * SEQ * SEQ + (size_t)q0 * SEQ;
    for (int kt = 0; kt < SEQ; kt += 64) {
#pragma unroll
        for (int s = tid; s < 4096; s += 256) {
            int r = s >> 6, c = s & 63;
            As[r][c] = arow[(size_t)r * SEQ + kt + c];
            Vs[r][c] = v[(size_t)(b*SEQ + kt + r) * D_MODEL + h*DK + c];
        }
        __syncthreads();
#pragma unroll 8
        for (int kk = 0; kk < 64; kk++) {
            float a[4], bb[4];
#pragma unroll
            for (int i = 0; i < 4; i++) a[i]  = As[ty*4 + i][kk];
#pragma unroll
            for (int j = 0; j < 4; j++) bb[j] = Vs[kk][tx*4 + j];
#pragma unroll
            for (int i = 0; i < 4; i++)
#pragma unroll
                for (int j = 0; j < 4; j++)
                    acc[i][j] = fmaf(a[i], bb[j], acc[i][j]);
        }
        __syncthreads();
    }
#pragma unroll
    for (int i = 0; i < 4; i++)
#pragma unroll
        for (int j = 0; j < 4; j++)
            ctx[(size_t)(b*SEQ + q0 + ty*4 + i) * D_MODEL + h*DK + tx*4 + j] =
                acc[i][j];
}

// ---------------- fused residual-add + LayerNorm (rows of 1024) --------------
__global__ __launch_bounds__(256) void add_ln_kernel(
    const float* __restrict__ a, const float* __restrict__ r,
    const float* __restrict__ g, const float* __restrict__ be,
    float* __restrict__ out)
{
    __shared__ float reds[8], reds2[8];
    __shared__ float s_mean, s_inv;
    const int row = blockIdx.x;
    const int tid = threadIdx.x;
    const float* pa = a + (size_t)row * D_MODEL;
    const float* pr = r + (size_t)row * D_MODEL;
    float vals[4];
    float s = 0.f, s2 = 0.f;
#pragma unroll
    for (int i = 0; i < 4; i++) {
        int c = tid + i * 256;
        float v = pa[c] + pr[c];
        vals[i] = v; s += v; s2 += v * v;
    }
#pragma unroll
    for (int o = 16; o > 0; o >>= 1) {
        s  += __shfl_xor_sync(~0u, s,  o);
        s2 += __shfl_xor_sync(~0u, s2, o);
    }
    if ((tid & 31) == 0) { reds[tid >> 5] = s; reds2[tid >> 5] = s2; }
    __syncthreads();
    if (tid < 32) {
        float v  = (tid < 8) ? reds[tid]  : 0.f;
        float v2 = (tid < 8) ? reds2[tid] : 0.f;
#pragma unroll
        for (int o = 4; o > 0; o >>= 1) {
            v  += __shfl_xor_sync(~0u, v,  o);
            v2 += __shfl_xor_sync(~0u, v2, o);
        }
        if (tid == 0) {
            float mean = v * (1.f / D_MODEL);
            float var  = v2 * (1.f / D_MODEL) - mean * mean;  // biased, = jnp.var
            s_mean = mean;
            s_inv  = rsqrtf(var + 1e-5f);
        }
    }
    __syncthreads();
    float mean = s_mean, inv = s_inv;
#pragma unroll
    for (int i = 0; i < 4; i++) {
        int c = tid + i * 256;
        out[(size_t)row * D_MODEL + c] = (vals[i] - mean) * inv * g[c] + be[c];
    }
}

// ---------------- launch -----------------------------------------------------
extern "C" void kernel_launch(void* const* d_in, const int* in_sizes, int n_in,
                              void* d_out, int out_size)
{
    const float* src = (const float*)d_in[0];
    const float* wq  = (const float*)d_in[1];
    const float* bq  = (const float*)d_in[2];
    const float* wk  = (const float*)d_in[3];
    const float* bk  = (const float*)d_in[4];
    const float* wv  = (const float*)d_in[5];
    const float* bv  = (const float*)d_in[6];
    const float* g1  = (const float*)d_in[7];
    const float* be1 = (const float*)d_in[8];
    const float* w1  = (const float*)d_in[9];
    const float* b1  = (const float*)d_in[10];
    const float* w2  = (const float*)d_in[11];
    const float* b2  = (const float*)d_in[12];
    const float* g2  = (const float*)d_in[13];
    const float* be2 = (const float*)d_in[14];
    float* out = (float*)d_out;

    float *pq, *pk, *pv, *patt, *pctx, *px, *ph, *py;
    cudaGetSymbolAddress((void**)&pq,   g_q);
    cudaGetSymbolAddress((void**)&pk,   g_k);
    cudaGetSymbolAddress((void**)&pv,   g_v);
    cudaGetSymbolAddress((void**)&patt, g_att);
    cudaGetSymbolAddress((void**)&pctx, g_ctx);
    cudaGetSymbolAddress((void**)&px,   g_x);
    cudaGetSymbolAddress((void**)&ph,   g_h);
    cudaGetSymbolAddress((void**)&py,   g_y);

    cudaFuncSetAttribute(gemm_tc_kernel<false>,
                         cudaFuncAttributeMaxDynamicSharedMemorySize, GEMM_SMEM);
    cudaFuncSetAttribute(gemm_tc_kernel<true>,
                         cudaFuncAttributeMaxDynamicSharedMemorySize, GEMM_SMEM);

    // QKV projections (tensor cores, 3xTF32)
    gemm_tc_kernel<false><<<dim3(D_MODEL/128, TOKENS/128), 256, GEMM_SMEM>>>(
        src, wq, bq, pq, TOKENS, D_MODEL, D_MODEL);
    gemm_tc_kernel<false><<<dim3(D_MODEL/128, TOKENS/128), 256, GEMM_SMEM>>>(
        src, wk, bk, pk, TOKENS, D_MODEL, D_MODEL);
    gemm_tc_kernel<false><<<dim3(D_MODEL/128, TOKENS/128), 256, GEMM_SMEM>>>(
        src, wv, bv, pv, TOKENS, D_MODEL, D_MODEL);

    // attention (SIMT for now)
    attn_scores_kernel<<<dim3(BH, SEQ/64, SEQ/64), 256>>>(pq, pk, patt);
    softmax_kernel<<<BH * SEQ, 256>>>(patt);
    attn_ctx_kernel<<<dim3(BH, SEQ/64), 256>>>(patt, pv, pctx);

    // residual + LN1
    add_ln_kernel<<<TOKENS, 256>>>(pctx, src, g1, be1, px);

    // FFN (tensor cores)
    gemm_tc_kernel<true><<<dim3(FEED/128, TOKENS/128), 256, GEMM_SMEM>>>(
        px, w1, b1, ph, TOKENS, FEED, D_MODEL);
    gemm_tc_kernel<false><<<dim3(D_MODEL/128, TOKENS/128), 256, GEMM_SMEM>>>(
        ph, w2, b2, py, TOKENS, D_MODEL, FEED);

    // residual + LN2 -> output
    add_ln_kernel<<<TOKENS, 256>>>(py, px, g2, be2, out);
}

// round 5
// speedup vs baseline: 1.4364x; 1.1241x over previous
#include <cuda_runtime.h>
#include <math.h>
#include <stdint.h>

#define D_MODEL 1024
#define FEED    4096
#define HEADS   16
#define DK      64
#define SEQ     512
#define BATCH   8
#define TOKENS  (BATCH*SEQ)    // 4096
#define BH      (BATCH*HEADS)  // 128

// ---------------- scratch (no allocations allowed) ----------------
__device__ float g_q  [TOKENS*(size_t)D_MODEL];
__device__ float g_k  [TOKENS*(size_t)D_MODEL];
__device__ float g_v  [TOKENS*(size_t)D_MODEL];
__device__ float g_ctx[TOKENS*(size_t)D_MODEL];
__device__ float g_x  [TOKENS*(size_t)D_MODEL];
__device__ float g_h  [TOKENS*(size_t)FEED];      // 64 MB
__device__ float g_y  [TOKENS*(size_t)D_MODEL];

// ======================= common MMA helpers =======================
#define CP_ASYNC16(dst_u32, src) \
    asm volatile("cp.async.cg.shared.global [%0], [%1], 16;" \
                 :: "r"(dst_u32), "l"(src) : "memory")
#define CP_COMMIT()  asm volatile("cp.async.commit_group;" ::: "memory")
#define CP_WAIT1()   asm volatile("cp.async.wait_group 1;" ::: "memory")
#define CP_WAIT0()   asm volatile("cp.async.wait_group 0;" ::: "memory")

#define MMA_TF32(d, a0,a1,a2,a3, b0,b1) \
    asm volatile("mma.sync.aligned.m16n8k8.row.col.f32.tf32.tf32.f32 " \
        "{%0,%1,%2,%3}, {%4,%5,%6,%7}, {%8,%9}, {%0,%1,%2,%3};" \
        : "+f"((d)[0]), "+f"((d)[1]), "+f"((d)[2]), "+f"((d)[3]) \
        : "r"(a0), "r"(a1), "r"(a2), "r"(a3), "r"(b0), "r"(b1))

__device__ __forceinline__ void tf32_split(float v, uint32_t& hi, uint32_t& lo) {
    uint32_t h = __float_as_uint(v) & 0xffffe000u;
    float lf = v - __uint_as_float(h);
    hi = h;
    lo = __float_as_uint(lf) & 0xffffe000u;
}

// ======================= mma.sync TF32 GEMM =======================
// C[M,N] = A[M,K] @ W[K,N] + bias (optional ReLU), 3xTF32 split.
// CTA tile 128x128, BK=32, 8 warps (warp tile 64x32), cp.async 2-stage pipeline.
#define APAD   36
#define BPAD   132
#define A_BYTES (128*APAD*4)        // 18432
#define B_BYTES (32*BPAD*4)         // 16896
#define STAGE_BYTES (A_BYTES + B_BYTES)  // 35328
#define GEMM_SMEM (2*STAGE_BYTES)        // 70656

template<bool RELU>
__global__ __launch_bounds__(256, 1) void gemm_tc_kernel(
    const float* __restrict__ A, const float* __restrict__ W,
    const float* __restrict__ bias, float* __restrict__ C,
    int M, int N, int K)
{
    extern __shared__ char smem[];
    const uint32_t sbase = (uint32_t)__cvta_generic_to_shared(smem);

    const int tid = threadIdx.x;
    const int wid = tid >> 5;
    const int lane = tid & 31;
    const int gid = lane >> 2;
    const int tig = lane & 3;
    const int wy = wid >> 2;
    const int wx = wid & 3;

    const int bm = blockIdx.y * 128;
    const int bn = blockIdx.x * 128;
    const int nC = K >> 5;

    float acc[4][4][4];
#pragma unroll
    for (int i = 0; i < 4; i++)
#pragma unroll
        for (int j = 0; j < 4; j++)
#pragma unroll
            for (int r = 0; r < 4; r++) acc[i][j][r] = 0.f;

    const int am[4] = { (tid + 0*256) >> 3, (tid + 1*256) >> 3,
                        (tid + 2*256) >> 3, (tid + 3*256) >> 3 };
    const int aq = tid & 7;
    const int bk4[4] = { (tid + 0*256) >> 5, (tid + 1*256) >> 5,
                         (tid + 2*256) >> 5, (tid + 3*256) >> 5 };
    const int bq = tid & 31;

    const float* Ab = A + (size_t)bm * K;

#define ISSUE_STAGE(c) do { \
    const int _s = (c) & 1; \
    const int _k0 = (c) << 5; \
    const uint32_t _sa = sbase + _s * STAGE_BYTES; \
    const uint32_t _sb = _sa + A_BYTES; \
    _Pragma("unroll") \
    for (int _i = 0; _i < 4; _i++) { \
        CP_ASYNC16(_sa + am[_i]*144 + aq*16, \
                   Ab + (size_t)am[_i]*K + _k0 + aq*4); \
    } \
    _Pragma("unroll") \
    for (int _i = 0; _i < 4; _i++) { \
        CP_ASYNC16(_sb + bk4[_i]*528 + bq*16, \
                   W + (size_t)(_k0 + bk4[_i])*N + bn + bq*4); \
    } \
    CP_COMMIT(); \
} while (0)

    ISSUE_STAGE(0);

    for (int c = 0; c < nC; c++) {
        if (c + 1 < nC) { ISSUE_STAGE(c + 1); CP_WAIT1(); }
        else            { CP_WAIT0(); }
        __syncthreads();

        const int s = c & 1;
        const float* pA = reinterpret_cast<const float*>(smem + s * STAGE_BYTES);
        const float* pB = reinterpret_cast<const float*>(smem + s * STAGE_BYTES + A_BYTES);

#pragma unroll
        for (int ks = 0; ks < 4; ks++) {
            const int k0 = ks * 8;
            uint32_t Ah[4][4], Al[4][4];
#pragma unroll
            for (int mt = 0; mt < 4; mt++) {
                const int r0 = wy*64 + mt*16 + gid;
                float v0 = pA[(r0    )*APAD + k0 + tig    ];
                float v1 = pA[(r0 + 8)*APAD + k0 + tig    ];
                float v2 = pA[(r0    )*APAD + k0 + tig + 4];
                float v3 = pA[(r0 + 8)*APAD + k0 + tig + 4];
                tf32_split(v0, Ah[mt][0], Al[mt][0]);
                tf32_split(v1, Ah[mt][1], Al[mt][1]);
                tf32_split(v2, Ah[mt][2], Al[mt][2]);
                tf32_split(v3, Ah[mt][3], Al[mt][3]);
            }
            uint32_t Bh[4][2], Bl[4][2];
#pragma unroll
            for (int nt = 0; nt < 4; nt++) {
                const int nc0 = wx*32 + nt*8 + gid;
                float v0 = pB[(k0 + tig    )*BPAD + nc0];
                float v1 = pB[(k0 + tig + 4)*BPAD + nc0];
                tf32_split(v0, Bh[nt][0], Bl[nt][0]);
                tf32_split(v1, Bh[nt][1], Bl[nt][1]);
            }
#pragma unroll
            for (int mt = 0; mt < 4; mt++) {
#pragma unroll
                for (int nt = 0; nt < 4; nt++) {
                    MMA_TF32(acc[mt][nt], Ah[mt][0], Ah[mt][1], Ah[mt][2], Ah[mt][3],
                             Bh[nt][0], Bh[nt][1]);
                    MMA_TF32(acc[mt][nt], Al[mt][0], Al[mt][1], Al[mt][2], Al[mt][3],
                             Bh[nt][0], Bh[nt][1]);
                    MMA_TF32(acc[mt][nt], Ah[mt][0], Ah[mt][1], Ah[mt][2], Ah[mt][3],
                             Bl[nt][0], Bl[nt][1]);
                }
            }
        }
        __syncthreads();
    }

#pragma unroll
    for (int nt = 0; nt < 4; nt++) {
        const int cc = bn + wx*32 + nt*8 + tig*2;
        const float b0 = bias[cc], b1 = bias[cc + 1];
#pragma unroll
        for (int mt = 0; mt < 4; mt++) {
            const int r0 = bm + wy*64 + mt*16 + gid;
            float v0 = acc[mt][nt][0] + b0;
            float v1 = acc[mt][nt][1] + b1;
            float v2 = acc[mt][nt][2] + b0;
            float v3 = acc[mt][nt][3] + b1;
            if (RELU) {
                v0 = fmaxf(v0, 0.f); v1 = fmaxf(v1, 0.f);
                v2 = fmaxf(v2, 0.f); v3 = fmaxf(v3, 0.f);
            }
            *reinterpret_cast<float2*>(C + (size_t)r0 * N + cc)       = make_float2(v0, v1);
            *reinterpret_cast<float2*>(C + (size_t)(r0 + 8) * N + cc) = make_float2(v2, v3);
        }
    }
#undef ISSUE_STAGE
}

// ======================= fused flash attention ====================
// One CTA per (bh, 128-row q tile). grid (BH, SEQ/128). 256 threads, 8 warps.
// S = Q@K^T (tf32 3x split) -> online softmax in smem -> O += P@V (tf32 3x split).
// Writes ctx in head-concat layout. g_att never materialized.
#define QP   68
#define KTP  132
#define VP   68
#define SP   132
#define FA_Q_OFF   0
#define FA_KT_OFF  (FA_Q_OFF  + 128*QP*4)         // 34816
#define FA_V_OFF   (FA_KT_OFF + 64*KTP*4)         // 68608
#define FA_S_OFF   (FA_V_OFF  + 128*VP*4)         // 103424
#define FA_M_OFF   (FA_S_OFF  + 128*SP*4)         // 170.0 KB
#define FA_L_OFF   (FA_M_OFF  + 128*4)
#define FA_AL_OFF  (FA_L_OFF  + 128*4)
#define FA_SMEM    (FA_AL_OFF + 128*4)            // 172544

__global__ __launch_bounds__(256, 1) void flash_attn_kernel(
    const float* __restrict__ q, const float* __restrict__ k,
    const float* __restrict__ v, float* __restrict__ ctx)
{
    extern __shared__ char smem[];
    float* Qs  = reinterpret_cast<float*>(smem + FA_Q_OFF);
    float* KTs = reinterpret_cast<float*>(smem + FA_KT_OFF);
    float* Vs  = reinterpret_cast<float*>(smem + FA_V_OFF);
    float* Ss  = reinterpret_cast<float*>(smem + FA_S_OFF);
    float* m_s = reinterpret_cast<float*>(smem + FA_M_OFF);
    float* l_s = reinterpret_cast<float*>(smem + FA_L_OFF);
    float* al_s= reinterpret_cast<float*>(smem + FA_AL_OFF);

    const int tid = threadIdx.x;
    const int wid = tid >> 5;
    const int lane = tid & 31;
    const int gid = lane >> 2;
    const int tig = lane & 3;

    const int bh = blockIdx.x;
    const int b  = bh >> 4, h = bh & 15;
    const int q0 = blockIdx.y * 128;

    // load Q tile [128 x 64]
    const float* qg = q + (size_t)(b*SEQ + q0) * D_MODEL + h*DK;
#pragma unroll
    for (int i = 0; i < 8; i++) {
        int idx = tid + i * 256;
        int row = idx >> 4, d4 = idx & 15;
        float4 vv = *reinterpret_cast<const float4*>(qg + (size_t)row * D_MODEL + d4*4);
        *reinterpret_cast<float4*>(Qs + row*QP + d4*4) = vv;
    }
    if (tid < 128) { m_s[tid] = -INFINITY; l_s[tid] = 0.f; }

    // O accumulators: warp tile 32x32 over 128x64 output
    const int wy2 = wid >> 1;      // 0..3
    const int wx2 = wid & 1;       // 0..1
    float acc_o[2][4][4];
#pragma unroll
    for (int mt = 0; mt < 2; mt++)
#pragma unroll
        for (int nt = 0; nt < 4; nt++)
#pragma unroll
            for (int r = 0; r < 4; r++) acc_o[mt][nt][r] = 0.f;

    // S warp tile 64x32 over 128x128
    const int wy = wid >> 2;       // 0..1
    const int wx = wid & 3;        // 0..3

    for (int kt = 0; kt < 4; kt++) {
        __syncthreads();   // protect K/V smem from previous PV reads
        const int s0 = kt * 128;
        // K tile -> transposed smem [d][s]
        const float* kg = k + (size_t)(b*SEQ + s0) * D_MODEL + h*DK;
        const float* vg = v + (size_t)(b*SEQ + s0) * D_MODEL + h*DK;
#pragma unroll
        for (int i = 0; i < 8; i++) {
            int idx = tid + i * 256;
            int srow = idx >> 4, d4 = idx & 15;
            float4 vv = *reinterpret_cast<const float4*>(kg + (size_t)srow * D_MODEL + d4*4);
            KTs[(d4*4+0)*KTP + srow] = vv.x;
            KTs[(d4*4+1)*KTP + srow] = vv.y;
            KTs[(d4*4+2)*KTP + srow] = vv.z;
            KTs[(d4*4+3)*KTP + srow] = vv.w;
        }
#pragma unroll
        for (int i = 0; i < 8; i++) {
            int idx = tid + i * 256;
            int srow = idx >> 4, d4 = idx & 15;
            float4 vv = *reinterpret_cast<const float4*>(vg + (size_t)srow * D_MODEL + d4*4);
            *reinterpret_cast<float4*>(Vs + srow*VP + d4*4) = vv;
        }
        __syncthreads();

        // ---- S = Q @ K^T (128x128, k=64) ----
        float s_acc[4][4][4];
#pragma unroll
        for (int i = 0; i < 4; i++)
#pragma unroll
            for (int j = 0; j < 4; j++)
#pragma unroll
                for (int r = 0; r < 4; r++) s_acc[i][j][r] = 0.f;

#pragma unroll
        for (int ks = 0; ks < 8; ks++) {
            const int k0 = ks * 8;
            uint32_t Ah[4][4], Al[4][4];
#pragma unroll
            for (int mt = 0; mt < 4; mt++) {
                const int r0 = wy*64 + mt*16 + gid;
                tf32_split(Qs[(r0    )*QP + k0 + tig    ], Ah[mt][0], Al[mt][0]);
                tf32_split(Qs[(r0 + 8)*QP + k0 + tig    ], Ah[mt][1], Al[mt][1]);
                tf32_split(Qs[(r0    )*QP + k0 + tig + 4], Ah[mt][2], Al[mt][2]);
                tf32_split(Qs[(r0 + 8)*QP + k0 + tig + 4], Ah[mt][3], Al[mt][3]);
            }
            uint32_t Bh[4][2], Bl[4][2];
#pragma unroll
            for (int nt = 0; nt < 4; nt++) {
                const int nc0 = wx*32 + nt*8 + gid;
                tf32_split(KTs[(k0 + tig    )*KTP + nc0], Bh[nt][0], Bl[nt][0]);
                tf32_split(KTs[(k0 + tig + 4)*KTP + nc0], Bh[nt][1], Bl[nt][1]);
            }
#pragma unroll
            for (int mt = 0; mt < 4; mt++)
#pragma unroll
                for (int nt = 0; nt < 4; nt++) {
                    MMA_TF32(s_acc[mt][nt], Ah[mt][0], Ah[mt][1], Ah[mt][2], Ah[mt][3],
                             Bh[nt][0], Bh[nt][1]);
                    MMA_TF32(s_acc[mt][nt], Al[mt][0], Al[mt][1], Al[mt][2], Al[mt][3],
                             Bh[nt][0], Bh[nt][1]);
                    MMA_TF32(s_acc[mt][nt], Ah[mt][0], Ah[mt][1], Ah[mt][2], Ah[mt][3],
                             Bl[nt][0], Bl[nt][1]);
                }
        }
        // write scaled scores to smem
#pragma unroll
        for (int mt = 0; mt < 4; mt++) {
            const int r0 = wy*64 + mt*16 + gid;
#pragma unroll
            for (int nt = 0; nt < 4; nt++) {
                const int cc = wx*32 + nt*8 + tig*2;
                *reinterpret_cast<float2*>(Ss + r0*SP + cc) =
                    make_float2(s_acc[mt][nt][0]*0.125f, s_acc[mt][nt][1]*0.125f);
                *reinterpret_cast<float2*>(Ss + (r0+8)*SP + cc) =
                    make_float2(s_acc[mt][nt][2]*0.125f, s_acc[mt][nt][3]*0.125f);
            }
        }
        __syncthreads();

        // ---- online softmax: 2 threads per row ----
        {
            const int row = tid >> 1;
            const int half = tid & 1;
            float* p = Ss + row*SP + half*64;
            float mx = -INFINITY;
#pragma unroll 16
            for (int j = 0; j < 64; j++) mx = fmaxf(mx, p[j]);
            mx = fmaxf(mx, __shfl_xor_sync(0xffffffffu, mx, 1));
            const float m_old = m_s[row];
            const float m_new = fmaxf(m_old, mx);
            float sum = 0.f;
#pragma unroll 16
            for (int j = 0; j < 64; j++) {
                float e = __expf(p[j] - m_new);
                p[j] = e; sum += e;
            }
            sum += __shfl_xor_sync(0xffffffffu, sum, 1);
            if (half == 0) {
                const float al = __expf(m_old - m_new);
                l_s[row] = al * l_s[row] + sum;
                m_s[row] = m_new;
                al_s[row] = al;
            }
        }
        __syncthreads();

        // ---- O = alpha*O + P @ V (128x64, k=128) ----
#pragma unroll
        for (int mt = 0; mt < 2; mt++) {
            const int r0 = wy2*32 + mt*16 + gid;
            const float aL = al_s[r0];
            const float aH = al_s[r0 + 8];
#pragma unroll
            for (int nt = 0; nt < 4; nt++) {
                acc_o[mt][nt][0] *= aL; acc_o[mt][nt][1] *= aL;
                acc_o[mt][nt][2] *= aH; acc_o[mt][nt][3] *= aH;
            }
        }
#pragma unroll
        for (int ks = 0; ks < 16; ks++) {
            const int k0 = ks * 8;
            uint32_t Ah[2][4], Al[2][4];
#pragma unroll
            for (int mt = 0; mt < 2; mt++) {
                const int r0 = wy2*32 + mt*16 + gid;
                tf32_split(Ss[(r0    )*SP + k0 + tig    ], Ah[mt][0], Al[mt][0]);
                tf32_split(Ss[(r0 + 8)*SP + k0 + tig    ], Ah[mt][1], Al[mt][1]);
                tf32_split(Ss[(r0    )*SP + k0 + tig + 4], Ah[mt][2], Al[mt][2]);
                tf32_split(Ss[(r0 + 8)*SP + k0 + tig + 4], Ah[mt][3], Al[mt][3]);
            }
            uint32_t Bh[4][2], Bl[4][2];
#pragma unroll
            for (int nt = 0; nt < 4; nt++) {
                const int dc = wx2*32 + nt*8 + gid;
                tf32_split(Vs[(k0 + tig    )*VP + dc], Bh[nt][0], Bl[nt][0]);
                tf32_split(Vs[(k0 + tig + 4)*VP + dc], Bh[nt][1], Bl[nt][1]);
            }
#pragma unroll
            for (int mt = 0; mt < 2; mt++)
#pragma unroll
                for (int nt = 0; nt < 4; nt++) {
                    MMA_TF32(acc_o[mt][nt], Ah[mt][0], Ah[mt][1], Ah[mt][2], Ah[mt][3],
                             Bh[nt][0], Bh[nt][1]);
                    MMA_TF32(acc_o[mt][nt], Al[mt][0], Al[mt][1], Al[mt][2], Al[mt][3],
                             Bh[nt][0], Bh[nt][1]);
                    MMA_TF32(acc_o[mt][nt], Ah[mt][0], Ah[mt][1], Ah[mt][2], Ah[mt][3],
                             Bl[nt][0], Bl[nt][1]);
                }
        }
    }

    // ---- finalize: O /= l, write ctx head-concat ----
    __syncthreads();
#pragma unroll
    for (int mt = 0; mt < 2; mt++) {
        const int r0 = wy2*32 + mt*16 + gid;
        const float iL = 1.f / l_s[r0];
        const float iH = 1.f / l_s[r0 + 8];
#pragma unroll
        for (int nt = 0; nt < 4; nt++) {
            const int dc = h*DK + wx2*32 + nt*8 + tig*2;
            const size_t rowL = (size_t)(b*SEQ + q0 + r0);
            *reinterpret_cast<float2*>(ctx + rowL * D_MODEL + dc) =
                make_float2(acc_o[mt][nt][0]*iL, acc_o[mt][nt][1]*iL);
            *reinterpret_cast<float2*>(ctx + (rowL+8) * D_MODEL + dc) =
                make_float2(acc_o[mt][nt][2]*iH, acc_o[mt][nt][3]*iH);
        }
    }
}

// ---------------- fused residual-add + LayerNorm (rows of 1024) --------------
__global__ __launch_bounds__(256) void add_ln_kernel(
    const float* __restrict__ a, const float* __restrict__ r,
    const float* __restrict__ g, const float* __restrict__ be,
    float* __restrict__ out)
{
    __shared__ float reds[8], reds2[8];
    __shared__ float s_mean, s_inv;
    const int row = blockIdx.x;
    const int tid = threadIdx.x;
    const float* pa = a + (size_t)row * D_MODEL;
    const float* pr = r + (size_t)row * D_MODEL;
    float vals[4];
    float s = 0.f, s2 = 0.f;
#pragma unroll
    for (int i = 0; i < 4; i++) {
        int c = tid + i * 256;
        float v = pa[c] + pr[c];
        vals[i] = v; s += v; s2 += v * v;
    }
#pragma unroll
    for (int o = 16; o > 0; o >>= 1) {
        s  += __shfl_xor_sync(~0u, s,  o);
        s2 += __shfl_xor_sync(~0u, s2, o);
    }
    if ((tid & 31) == 0) { reds[tid >> 5] = s; reds2[tid >> 5] = s2; }
    __syncthreads();
    if (tid < 32) {
        float v  = (tid < 8) ? reds[tid]  : 0.f;
        float v2 = (tid < 8) ? reds2[tid] : 0.f;
#pragma unroll
        for (int o = 4; o > 0; o >>= 1) {
            v  += __shfl_xor_sync(~0u, v,  o);
            v2 += __shfl_xor_sync(~0u, v2, o);
        }
        if (tid == 0) {
            float mean = v * (1.f / D_MODEL);
            float var  = v2 * (1.f / D_MODEL) - mean * mean;  // biased, = jnp.var
            s_mean = mean;
            s_inv  = rsqrtf(var + 1e-5f);
        }
    }
    __syncthreads();
    float mean = s_mean, inv = s_inv;
#pragma unroll
    for (int i = 0; i < 4; i++) {
        int c = tid + i * 256;
        out[(size_t)row * D_MODEL + c] = (vals[i] - mean) * inv * g[c] + be[c];
    }
}

// ---------------- launch -----------------------------------------------------
extern "C" void kernel_launch(void* const* d_in, const int* in_sizes, int n_in,
                              void* d_out, int out_size)
{
    const float* src = (const float*)d_in[0];
    const float* wq  = (const float*)d_in[1];
    const float* bq  = (const float*)d_in[2];
    const float* wk  = (const float*)d_in[3];
    const float* bk  = (const float*)d_in[4];
    const float* wv  = (const float*)d_in[5];
    const float* bv  = (const float*)d_in[6];
    const float* g1  = (const float*)d_in[7];
    const float* be1 = (const float*)d_in[8];
    const float* w1  = (const float*)d_in[9];
    const float* b1  = (const float*)d_in[10];
    const float* w2  = (const float*)d_in[11];
    const float* b2  = (const float*)d_in[12];
    const float* g2  = (const float*)d_in[13];
    const float* be2 = (const float*)d_in[14];
    float* out = (float*)d_out;

    float *pq, *pk, *pv, *pctx, *px, *ph, *py;
    cudaGetSymbolAddress((void**)&pq,   g_q);
    cudaGetSymbolAddress((void**)&pk,   g_k);
    cudaGetSymbolAddress((void**)&pv,   g_v);
    cudaGetSymbolAddress((void**)&pctx, g_ctx);
    cudaGetSymbolAddress((void**)&px,   g_x);
    cudaGetSymbolAddress((void**)&ph,   g_h);
    cudaGetSymbolAddress((void**)&py,   g_y);

    cudaFuncSetAttribute(gemm_tc_kernel<false>,
                         cudaFuncAttributeMaxDynamicSharedMemorySize, GEMM_SMEM);
    cudaFuncSetAttribute(gemm_tc_kernel<true>,
                         cudaFuncAttributeMaxDynamicSharedMemorySize, GEMM_SMEM);
    cudaFuncSetAttribute(flash_attn_kernel,
                         cudaFuncAttributeMaxDynamicSharedMemorySize, FA_SMEM);

    // QKV projections (tensor cores, 3xTF32)
    gemm_tc_kernel<false><<<dim3(D_MODEL/128, TOKENS/128), 256, GEMM_SMEM>>>(
        src, wq, bq, pq, TOKENS, D_MODEL, D_MODEL);
    gemm_tc_kernel<false><<<dim3(D_MODEL/128, TOKENS/128), 256, GEMM_SMEM>>>(
        src, wk, bk, pk, TOKENS, D_MODEL, D_MODEL);
    gemm_tc_kernel<false><<<dim3(D_MODEL/128, TOKENS/128), 256, GEMM_SMEM>>>(
        src, wv, bv, pv, TOKENS, D_MODEL, D_MODEL);

    // fused flash attention (no materialized att matrix)
    flash_attn_kernel<<<dim3(BH, SEQ/128), 256, FA_SMEM>>>(pq, pk, pv, pctx);

    // residual + LN1
    add_ln_kernel<<<TOKENS, 256>>>(pctx, src, g1, be1, px);

    // FFN (tensor cores)
    gemm_tc_kernel<true><<<dim3(FEED/128, TOKENS/128), 256, GEMM_SMEM>>>(
        px, w1, b1, ph, TOKENS, FEED, D_MODEL);
    gemm_tc_kernel<false><<<dim3(D_MODEL/128, TOKENS/128), 256, GEMM_SMEM>>>(
        ph, w2, b2, py, TOKENS, D_MODEL, FEED);

    // residual + LN2 -> output
    add_ln_kernel<<<TOKENS, 256>>>(py, px, g2, be2, out);
}

// round 6
// speedup vs baseline: 2.1455x; 1.4936x over previous
#include <cuda_runtime.h>
#include <cuda_bf16.h>
#include <math.h>
#include <stdint.h>

#define D_MODEL 1024
#define FEED    4096
#define HEADS   16
#define DK      64
#define SEQ     512
#define BATCH   8
#define TOKENS  (BATCH*SEQ)    // 4096
#define BH      (BATCH*HEADS)  // 128

// ---------------- scratch (no allocations allowed) ----------------
__device__ float g_q  [TOKENS*(size_t)D_MODEL];
__device__ float g_k  [TOKENS*(size_t)D_MODEL];
__device__ float g_v  [TOKENS*(size_t)D_MODEL];
__device__ float g_ctx[TOKENS*(size_t)D_MODEL];
__device__ float g_x  [TOKENS*(size_t)D_MODEL];
__device__ float g_y  [TOKENS*(size_t)D_MODEL];
// packed bf16 hi/lo operands (k-pair packed: u32 = [bf16(k+1)<<16 | bf16(k)])
__device__ uint32_t g_srcp_hi[TOKENS*(size_t)(D_MODEL/2)];
__device__ uint32_t g_srcp_lo[TOKENS*(size_t)(D_MODEL/2)];
__device__ uint32_t g_xp_hi  [TOKENS*(size_t)(D_MODEL/2)];
__device__ uint32_t g_xp_lo  [TOKENS*(size_t)(D_MODEL/2)];
__device__ uint32_t g_hp_hi  [TOKENS*(size_t)(FEED/2)];    // 32 MB
__device__ uint32_t g_hp_lo  [TOKENS*(size_t)(FEED/2)];
__device__ uint32_t g_wqp_hi [(size_t)(D_MODEL/2)*D_MODEL];
__device__ uint32_t g_wqp_lo [(size_t)(D_MODEL/2)*D_MODEL];
__device__ uint32_t g_wkp_hi [(size_t)(D_MODEL/2)*D_MODEL];
__device__ uint32_t g_wkp_lo [(size_t)(D_MODEL/2)*D_MODEL];
__device__ uint32_t g_wvp_hi [(size_t)(D_MODEL/2)*D_MODEL];
__device__ uint32_t g_wvp_lo [(size_t)(D_MODEL/2)*D_MODEL];
__device__ uint32_t g_w1p_hi [(size_t)(D_MODEL/2)*FEED];
__device__ uint32_t g_w1p_lo [(size_t)(D_MODEL/2)*FEED];
__device__ uint32_t g_w2p_hi [(size_t)(FEED/2)*D_MODEL];
__device__ uint32_t g_w2p_lo [(size_t)(FEED/2)*D_MODEL];

// ======================= helpers =======================
#define CP_ASYNC16(dst_u32, src) \
    asm volatile("cp.async.cg.shared.global [%0], [%1], 16;" \
                 :: "r"(dst_u32), "l"(src) : "memory")
#define CP_COMMIT()  asm volatile("cp.async.commit_group;" ::: "memory")
#define CP_WAIT2()   asm volatile("cp.async.wait_group 2;" ::: "memory")
#define CP_WAIT1()   asm volatile("cp.async.wait_group 1;" ::: "memory")
#define CP_WAIT0()   asm volatile("cp.async.wait_group 0;" ::: "memory")

#define MMA_TF32(d, a0,a1,a2,a3, b0,b1) \
    asm volatile("mma.sync.aligned.m16n8k8.row.col.f32.tf32.tf32.f32 " \
        "{%0,%1,%2,%3}, {%4,%5,%6,%7}, {%8,%9}, {%0,%1,%2,%3};" \
        : "+f"((d)[0]), "+f"((d)[1]), "+f"((d)[2]), "+f"((d)[3]) \
        : "r"(a0), "r"(a1), "r"(a2), "r"(a3), "r"(b0), "r"(b1))

#define MMA_BF16(d, a0,a1,a2,a3, b0,b1) \
    asm volatile("mma.sync.aligned.m16n8k16.row.col.f32.bf16.bf16.f32 " \
        "{%0,%1,%2,%3}, {%4,%5,%6,%7}, {%8,%9}, {%0,%1,%2,%3};" \
        : "+f"((d)[0]), "+f"((d)[1]), "+f"((d)[2]), "+f"((d)[3]) \
        : "r"(a0), "r"(a1), "r"(a2), "r"(a3), "r"(b0), "r"(b1))

__device__ __forceinline__ void tf32_split(float v, uint32_t& hi, uint32_t& lo) {
    uint32_t h = __float_as_uint(v) & 0xffffe000u;
    float lf = v - __uint_as_float(h);
    hi = h;
    lo = __float_as_uint(lf) & 0xffffe000u;
}

// split-pack two consecutive-k fp32 values into bf16x2 hi and lo words
__device__ __forceinline__ void split_pack(float v0, float v1,
                                           uint32_t& hi, uint32_t& lo) {
    __nv_bfloat162 h = __floats2bfloat162_rn(v0, v1);
    float r0 = v0 - __bfloat162float(h.x);
    float r1 = v1 - __bfloat162float(h.y);
    __nv_bfloat162 l = __floats2bfloat162_rn(r0, r1);
    hi = *reinterpret_cast<uint32_t*>(&h);
    lo = *reinterpret_cast<uint32_t*>(&l);
}

// ======================= pack kernels =======================
// activation [M,K] row-major -> packed [M, K/2] (linear in memory)
__global__ __launch_bounds__(256) void pack_act_kernel(
    const float* __restrict__ X, uint32_t* __restrict__ Xhi,
    uint32_t* __restrict__ Xlo, int total4)
{
    int id = blockIdx.x * 256 + threadIdx.x;
    if (id >= total4) return;
    float4 v = *reinterpret_cast<const float4*>(X + (size_t)id * 4);
    uint32_t h0, l0, h1, l1;
    split_pack(v.x, v.y, h0, l0);
    split_pack(v.z, v.w, h1, l1);
    *reinterpret_cast<uint2*>(Xhi + (size_t)id * 2) = make_uint2(h0, h1);
    *reinterpret_cast<uint2*>(Xlo + (size_t)id * 2) = make_uint2(l0, l1);
}

// weight W[K,N] -> packed [K/2, N]: word (kp,n) = pack(W[2kp][n], W[2kp+1][n])
__global__ __launch_bounds__(256) void pack_weight_kernel(
    const float* __restrict__ W, uint32_t* __restrict__ Bhi,
    uint32_t* __restrict__ Blo, int Kp, int N)
{
    int id = blockIdx.x * 256 + threadIdx.x;
    int n4cnt = N >> 2;
    if (id >= Kp * n4cnt) return;
    int kp = id / n4cnt, n4 = id % n4cnt;
    float4 w0 = *reinterpret_cast<const float4*>(W + (size_t)(2*kp)   * N + n4*4);
    float4 w1 = *reinterpret_cast<const float4*>(W + (size_t)(2*kp+1) * N + n4*4);
    uint32_t h[4], l[4];
    split_pack(w0.x, w1.x, h[0], l[0]);
    split_pack(w0.y, w1.y, h[1], l[1]);
    split_pack(w0.z, w1.z, h[2], l[2]);
    split_pack(w0.w, w1.w, h[3], l[3]);
    *reinterpret_cast<uint4*>(Bhi + (size_t)kp * N + n4*4) = make_uint4(h[0],h[1],h[2],h[3]);
    *reinterpret_cast<uint4*>(Blo + (size_t)kp * N + n4*4) = make_uint4(l[0],l[1],l[2],l[3]);
}

// ======================= bf16x3 GEMM =======================
// C[M,N] = A[M,K] @ W[K,N] + bias. A,B given as packed bf16 hi/lo.
// CTA 128x128, BK=32 fp32 (16 k-pairs), 8 warps (warp tile 64x32), 3-stage cp.async.
// smem per stage (u32): Ahi 128x20, Alo 128x20, Bhi 16x136, Blo 16x136
#define AW 20
#define BW 136
#define ST_AHI 0
#define ST_ALO 10240
#define ST_BHI 20480
#define ST_BLO 29184
#define ST_BYTES 37888
#define GEMM_SMEM (3*ST_BYTES)   // 113664

template<bool RELU, bool PACK_OUT>
__global__ __launch_bounds__(256, 1) void gemm_bf16_kernel(
    const uint32_t* __restrict__ Ahi, const uint32_t* __restrict__ Alo,
    const uint32_t* __restrict__ Bhi, const uint32_t* __restrict__ Blo,
    const float* __restrict__ bias, float* __restrict__ C,
    uint32_t* __restrict__ Ohi, uint32_t* __restrict__ Olo,
    int M, int N, int K)
{
    extern __shared__ char smem[];
    const uint32_t sbase = (uint32_t)__cvta_generic_to_shared(smem);

    const int tid = threadIdx.x;
    const int wid = tid >> 5;
    const int lane = tid & 31;
    const int gid = lane >> 2;
    const int tig = lane & 3;
    const int wy = wid >> 2;
    const int wx = wid & 3;

    const int bm = blockIdx.y * 128;
    const int bn = blockIdx.x * 128;
    const int Kp = K >> 1;
    const int nC = K >> 5;

    float acc[4][4][4];
#pragma unroll
    for (int i = 0; i < 4; i++)
#pragma unroll
        for (int j = 0; j < 4; j++)
#pragma unroll
            for (int r = 0; r < 4; r++) acc[i][j][r] = 0.f;

    const int ar[2] = { tid >> 2, (tid + 256) >> 2 };
    const int aq = tid & 3;
    const int bk[2] = { tid >> 5, (tid + 256) >> 5 };
    const int bq = tid & 31;

#define ISSUE(c) do { \
    const int _s = (c) % 3; \
    const int _kp0 = (c) << 4; \
    const uint32_t _sa = sbase + _s * ST_BYTES; \
    _Pragma("unroll") \
    for (int _i = 0; _i < 2; _i++) { \
        CP_ASYNC16(_sa + ST_AHI + ar[_i]*80 + aq*16, \
                   Ahi + (size_t)(bm + ar[_i])*Kp + _kp0 + aq*4); \
        CP_ASYNC16(_sa + ST_ALO + ar[_i]*80 + aq*16, \
                   Alo + (size_t)(bm + ar[_i])*Kp + _kp0 + aq*4); \
        CP_ASYNC16(_sa + ST_BHI + bk[_i]*544 + bq*16, \
                   Bhi + (size_t)(_kp0 + bk[_i])*N + bn + bq*4); \
        CP_ASYNC16(_sa + ST_BLO + bk[_i]*544 + bq*16, \
                   Blo + (size_t)(_kp0 + bk[_i])*N + bn + bq*4); \
    } \
    CP_COMMIT(); \
} while (0)

    ISSUE(0);
    ISSUE(1);

    for (int c = 0; c < nC; c++) {
        if (c + 2 < nC)      { ISSUE(c + 2); CP_WAIT2(); }
        else if (c + 1 < nC) { CP_WAIT1(); }
        else                 { CP_WAIT0(); }
        __syncthreads();

        const uint32_t* pAh = reinterpret_cast<const uint32_t*>(smem + (c % 3) * ST_BYTES);
        const uint32_t* pAl = pAh + 2560;
        const uint32_t* pBh = pAh + 5120;
        const uint32_t* pBl = pAh + 7296;

#pragma unroll
        for (int ks = 0; ks < 2; ks++) {
            const int kb = ks * 8;
            uint32_t Ah[4][4], Al[4][4];
#pragma unroll
            for (int mt = 0; mt < 4; mt++) {
                const int r0 = wy*64 + mt*16 + gid;
                Ah[mt][0] = pAh[(r0    )*AW + kb + tig    ];
                Ah[mt][1] = pAh[(r0 + 8)*AW + kb + tig    ];
                Ah[mt][2] = pAh[(r0    )*AW + kb + tig + 4];
                Ah[mt][3] = pAh[(r0 + 8)*AW + kb + tig + 4];
                Al[mt][0] = pAl[(r0    )*AW + kb + tig    ];
                Al[mt][1] = pAl[(r0 + 8)*AW + kb + tig    ];
                Al[mt][2] = pAl[(r0    )*AW + kb + tig + 4];
                Al[mt][3] = pAl[(r0 + 8)*AW + kb + tig + 4];
            }
            uint32_t Bh[4][2], Bl[4][2];
#pragma unroll
            for (int nt = 0; nt < 4; nt++) {
                const int col = wx*32 + nt*8 + gid;
                Bh[nt][0] = pBh[(kb + tig    )*BW + col];
                Bh[nt][1] = pBh[(kb + tig + 4)*BW + col];
                Bl[nt][0] = pBl[(kb + tig    )*BW + col];
                Bl[nt][1] = pBl[(kb + tig + 4)*BW + col];
            }
#pragma unroll
            for (int mt = 0; mt < 4; mt++)
#pragma unroll
                for (int nt = 0; nt < 4; nt++) {
                    MMA_BF16(acc[mt][nt], Ah[mt][0], Ah[mt][1], Ah[mt][2], Ah[mt][3],
                             Bh[nt][0], Bh[nt][1]);
                    MMA_BF16(acc[mt][nt], Al[mt][0], Al[mt][1], Al[mt][2], Al[mt][3],
                             Bh[nt][0], Bh[nt][1]);
                    MMA_BF16(acc[mt][nt], Ah[mt][0], Ah[mt][1], Ah[mt][2], Ah[mt][3],
                             Bl[nt][0], Bl[nt][1]);
                }
        }
        __syncthreads();
    }

    // epilogue
    const int Np = N >> 1;
#pragma unroll
    for (int nt = 0; nt < 4; nt++) {
        const int cc = bn + wx*32 + nt*8 + tig*2;
        const float b0 = bias[cc], b1 = bias[cc + 1];
#pragma unroll
        for (int mt = 0; mt < 4; mt++) {
            const int r0 = bm + wy*64 + mt*16 + gid;
            float v0 = acc[mt][nt][0] + b0;
            float v1 = acc[mt][nt][1] + b1;
            float v2 = acc[mt][nt][2] + b0;
            float v3 = acc[mt][nt][3] + b1;
            if (RELU) {
                v0 = fmaxf(v0, 0.f); v1 = fmaxf(v1, 0.f);
                v2 = fmaxf(v2, 0.f); v3 = fmaxf(v3, 0.f);
            }
            if (PACK_OUT) {
                uint32_t h, l;
                split_pack(v0, v1, h, l);
                Ohi[(size_t)r0 * Np + (cc >> 1)] = h;
                Olo[(size_t)r0 * Np + (cc >> 1)] = l;
                split_pack(v2, v3, h, l);
                Ohi[(size_t)(r0 + 8) * Np + (cc >> 1)] = h;
                Olo[(size_t)(r0 + 8) * Np + (cc >> 1)] = l;
            } else {
                *reinterpret_cast<float2*>(C + (size_t)r0 * N + cc)       = make_float2(v0, v1);
                *reinterpret_cast<float2*>(C + (size_t)(r0 + 8) * N + cc) = make_float2(v2, v3);
            }
        }
    }
#undef ISSUE
}

// ======================= fused flash attention (3xTF32) ====================
#define QP   68
#define KTP  132
#define VP   68
#define SP   132
#define FA_Q_OFF   0
#define FA_KT_OFF  (FA_Q_OFF  + 128*QP*4)
#define FA_V_OFF   (FA_KT_OFF + 64*KTP*4)
#define FA_S_OFF   (FA_V_OFF  + 128*VP*4)
#define FA_M_OFF   (FA_S_OFF  + 128*SP*4)
#define FA_L_OFF   (FA_M_OFF  + 128*4)
#define FA_AL_OFF  (FA_L_OFF  + 128*4)
#define FA_SMEM    (FA_AL_OFF + 128*4)

__global__ __launch_bounds__(256, 1) void flash_attn_kernel(
    const float* __restrict__ q, const float* __restrict__ k,
    const float* __restrict__ v, float* __restrict__ ctx)
{
    extern __shared__ char smem[];
    float* Qs  = reinterpret_cast<float*>(smem + FA_Q_OFF);
    float* KTs = reinterpret_cast<float*>(smem + FA_KT_OFF);
    float* Vs  = reinterpret_cast<float*>(smem + FA_V_OFF);
    float* Ss  = reinterpret_cast<float*>(smem + FA_S_OFF);
    float* m_s = reinterpret_cast<float*>(smem + FA_M_OFF);
    float* l_s = reinterpret_cast<float*>(smem + FA_L_OFF);
    float* al_s= reinterpret_cast<float*>(smem + FA_AL_OFF);

    const int tid = threadIdx.x;
    const int wid = tid >> 5;
    const int lane = tid & 31;
    const int gid = lane >> 2;
    const int tig = lane & 3;

    const int bh = blockIdx.x;
    const int b  = bh >> 4, h = bh & 15;
    const int q0 = blockIdx.y * 128;

    const float* qg = q + (size_t)(b*SEQ + q0) * D_MODEL + h*DK;
#pragma unroll
    for (int i = 0; i < 8; i++) {
        int idx = tid + i * 256;
        int row = idx >> 4, d4 = idx & 15;
        float4 vv = *reinterpret_cast<const float4*>(qg + (size_t)row * D_MODEL + d4*4);
        *reinterpret_cast<float4*>(Qs + row*QP + d4*4) = vv;
    }
    if (tid < 128) { m_s[tid] = -INFINITY; l_s[tid] = 0.f; }

    const int wy2 = wid >> 1;
    const int wx2 = wid & 1;
    float acc_o[2][4][4];
#pragma unroll
    for (int mt = 0; mt < 2; mt++)
#pragma unroll
        for (int nt = 0; nt < 4; nt++)
#pragma unroll
            for (int r = 0; r < 4; r++) acc_o[mt][nt][r] = 0.f;

    const int wy = wid >> 2;
    const int wx = wid & 3;

    for (int kt = 0; kt < 4; kt++) {
        __syncthreads();
        const int s0 = kt * 128;
        const float* kg = k + (size_t)(b*SEQ + s0) * D_MODEL + h*DK;
        const float* vg = v + (size_t)(b*SEQ + s0) * D_MODEL + h*DK;
#pragma unroll
        for (int i = 0; i < 8; i++) {
            int idx = tid + i * 256;
            int srow = idx >> 4, d4 = idx & 15;
            float4 vv = *reinterpret_cast<const float4*>(kg + (size_t)srow * D_MODEL + d4*4);
            KTs[(d4*4+0)*KTP + srow] = vv.x;
            KTs[(d4*4+1)*KTP + srow] = vv.y;
            KTs[(d4*4+2)*KTP + srow] = vv.z;
            KTs[(d4*4+3)*KTP + srow] = vv.w;
        }
#pragma unroll
        for (int i = 0; i < 8; i++) {
            int idx = tid + i * 256;
            int srow = idx >> 4, d4 = idx & 15;
            float4 vv = *reinterpret_cast<const float4*>(vg + (size_t)srow * D_MODEL + d4*4);
            *reinterpret_cast<float4*>(Vs + srow*VP + d4*4) = vv;
        }
        __syncthreads();

        float s_acc[4][4][4];
#pragma unroll
        for (int i = 0; i < 4; i++)
#pragma unroll
            for (int j = 0; j < 4; j++)
#pragma unroll
                for (int r = 0; r < 4; r++) s_acc[i][j][r] = 0.f;

#pragma unroll
        for (int ks = 0; ks < 8; ks++) {
            const int k0 = ks * 8;
            uint32_t Ah[4][4], Al[4][4];
#pragma unroll
            for (int mt = 0; mt < 4; mt++) {
                const int r0 = wy*64 + mt*16 + gid;
                tf32_split(Qs[(r0    )*QP + k0 + tig    ], Ah[mt][0], Al[mt][0]);
                tf32_split(Qs[(r0 + 8)*QP + k0 + tig    ], Ah[mt][1], Al[mt][1]);
                tf32_split(Qs[(r0    )*QP + k0 + tig + 4], Ah[mt][2], Al[mt][2]);
                tf32_split(Qs[(r0 + 8)*QP + k0 + tig + 4], Ah[mt][3], Al[mt][3]);
            }
            uint32_t Bh[4][2], Bl[4][2];
#pragma unroll
            for (int nt = 0; nt < 4; nt++) {
                const int nc0 = wx*32 + nt*8 + gid;
                tf32_split(KTs[(k0 + tig    )*KTP + nc0], Bh[nt][0], Bl[nt][0]);
                tf32_split(KTs[(k0 + tig + 4)*KTP + nc0], Bh[nt][1], Bl[nt][1]);
            }
#pragma unroll
            for (int mt = 0; mt < 4; mt++)
#pragma unroll
                for (int nt = 0; nt < 4; nt++) {
                    MMA_TF32(s_acc[mt][nt], Ah[mt][0], Ah[mt][1], Ah[mt][2], Ah[mt][3],
                             Bh[nt][0], Bh[nt][1]);
                    MMA_TF32(s_acc[mt][nt], Al[mt][0], Al[mt][1], Al[mt][2], Al[mt][3],
                             Bh[nt][0], Bh[nt][1]);
                    MMA_TF32(s_acc[mt][nt], Ah[mt][0], Ah[mt][1], Ah[mt][2], Ah[mt][3],
                             Bl[nt][0], Bl[nt][1]);
                }
        }
#pragma unroll
        for (int mt = 0; mt < 4; mt++) {
            const int r0 = wy*64 + mt*16 + gid;
#pragma unroll
            for (int nt = 0; nt < 4; nt++) {
                const int cc = wx*32 + nt*8 + tig*2;
                *reinterpret_cast<float2*>(Ss + r0*SP + cc) =
                    make_float2(s_acc[mt][nt][0]*0.125f, s_acc[mt][nt][1]*0.125f);
                *reinterpret_cast<float2*>(Ss + (r0+8)*SP + cc) =
                    make_float2(s_acc[mt][nt][2]*0.125f, s_acc[mt][nt][3]*0.125f);
            }
        }
        __syncthreads();

        {
            const int row = tid >> 1;
            const int half = tid & 1;
            float* p = Ss + row*SP + half*64;
            float mx = -INFINITY;
#pragma unroll 16
            for (int j = 0; j < 64; j++) mx = fmaxf(mx, p[j]);
            mx = fmaxf(mx, __shfl_xor_sync(0xffffffffu, mx, 1));
            const float m_old = m_s[row];
            const float m_new = fmaxf(m_old, mx);
            float sum = 0.f;
#pragma unroll 16
            for (int j = 0; j < 64; j++) {
                float e = __expf(p[j] - m_new);
                p[j] = e; sum += e;
            }
            sum += __shfl_xor_sync(0xffffffffu, sum, 1);
            if (half == 0) {
                const float al = __expf(m_old - m_new);
                l_s[row] = al * l_s[row] + sum;
                m_s[row] = m_new;
                al_s[row] = al;
            }
        }
        __syncthreads();

#pragma unroll
        for (int mt = 0; mt < 2; mt++) {
            const int r0 = wy2*32 + mt*16 + gid;
            const float aL = al_s[r0];
            const float aH = al_s[r0 + 8];
#pragma unroll
            for (int nt = 0; nt < 4; nt++) {
                acc_o[mt][nt][0] *= aL; acc_o[mt][nt][1] *= aL;
                acc_o[mt][nt][2] *= aH; acc_o[mt][nt][3] *= aH;
            }
        }
#pragma unroll
        for (int ks = 0; ks < 16; ks++) {
            const int k0 = ks * 8;
            uint32_t Ah[2][4], Al[2][4];
#pragma unroll
            for (int mt = 0; mt < 2; mt++) {
                const int r0 = wy2*32 + mt*16 + gid;
                tf32_split(Ss[(r0    )*SP + k0 + tig    ], Ah[mt][0], Al[mt][0]);
                tf32_split(Ss[(r0 + 8)*SP + k0 + tig    ], Ah[mt][1], Al[mt][1]);
                tf32_split(Ss[(r0    )*SP + k0 + tig + 4], Ah[mt][2], Al[mt][2]);
                tf32_split(Ss[(r0 + 8)*SP + k0 + tig + 4], Ah[mt][3], Al[mt][3]);
            }
            uint32_t Bh[4][2], Bl[4][2];
#pragma unroll
            for (int nt = 0; nt < 4; nt++) {
                const int dc = wx2*32 + nt*8 + gid;
                tf32_split(Vs[(k0 + tig    )*VP + dc], Bh[nt][0], Bl[nt][0]);
                tf32_split(Vs[(k0 + tig + 4)*VP + dc], Bh[nt][1], Bl[nt][1]);
            }
#pragma unroll
            for (int mt = 0; mt < 2; mt++)
#pragma unroll
                for (int nt = 0; nt < 4; nt++) {
                    MMA_TF32(acc_o[mt][nt], Ah[mt][0], Ah[mt][1], Ah[mt][2], Ah[mt][3],
                             Bh[nt][0], Bh[nt][1]);
                    MMA_TF32(acc_o[mt][nt], Al[mt][0], Al[mt][1], Al[mt][2], Al[mt][3],
                             Bh[nt][0], Bh[nt][1]);
                    MMA_TF32(acc_o[mt][nt], Ah[mt][0], Ah[mt][1], Ah[mt][2], Ah[mt][3],
                             Bl[nt][0], Bl[nt][1]);
                }
        }
    }

    __syncthreads();
#pragma unroll
    for (int mt = 0; mt < 2; mt++) {
        const int r0 = wy2*32 + mt*16 + gid;
        const float iL = 1.f / l_s[r0];
        const float iH = 1.f / l_s[r0 + 8];
#pragma unroll
        for (int nt = 0; nt < 4; nt++) {
            const int dc = h*DK + wx2*32 + nt*8 + tig*2;
            const size_t rowL = (size_t)(b*SEQ + q0 + r0);
            *reinterpret_cast<float2*>(ctx + rowL * D_MODEL + dc) =
                make_float2(acc_o[mt][nt][0]*iL, acc_o[mt][nt][1]*iL);
            *reinterpret_cast<float2*>(ctx + (rowL+8) * D_MODEL + dc) =
                make_float2(acc_o[mt][nt][2]*iH, acc_o[mt][nt][3]*iH);
        }
    }
}

// ---------------- fused residual-add + LayerNorm (+ optional bf16 packing) ---
template<bool PACK>
__global__ __launch_bounds__(256) void add_ln_kernel(
    const float* __restrict__ a, const float* __restrict__ r,
    const float* __restrict__ g, const float* __restrict__ be,
    float* __restrict__ out, uint32_t* __restrict__ Ohi,
    uint32_t* __restrict__ Olo)
{
    __shared__ float reds[8], reds2[8];
    __shared__ float s_mean, s_inv;
    const int row = blockIdx.x;
    const int tid = threadIdx.x;
    const int c0 = tid * 4;
    float4 va = *reinterpret_cast<const float4*>(a + (size_t)row * D_MODEL + c0);
    float4 vr = *reinterpret_cast<const float4*>(r + (size_t)row * D_MODEL + c0);
    float v0 = va.x + vr.x, v1 = va.y + vr.y, v2 = va.z + vr.z, v3 = va.w + vr.w;
    float s  = v0 + v1 + v2 + v3;
    float s2 = v0*v0 + v1*v1 + v2*v2 + v3*v3;
#pragma unroll
    for (int o = 16; o > 0; o >>= 1) {
        s  += __shfl_xor_sync(~0u, s,  o);
        s2 += __shfl_xor_sync(~0u, s2, o);
    }
    if ((tid & 31) == 0) { reds[tid >> 5] = s; reds2[tid >> 5] = s2; }
    __syncthreads();
    if (tid < 32) {
        float v  = (tid < 8) ? reds[tid]  : 0.f;
        float vv = (tid < 8) ? reds2[tid] : 0.f;
#pragma unroll
        for (int o = 4; o > 0; o >>= 1) {
            v  += __shfl_xor_sync(~0u, v,  o);
            vv += __shfl_xor_sync(~0u, vv, o);
        }
        if (tid == 0) {
            float mean = v * (1.f / D_MODEL);
            float var  = vv * (1.f / D_MODEL) - mean * mean;
            s_mean = mean;
            s_inv  = rsqrtf(var + 1e-5f);
        }
    }
    __syncthreads();
    const float mean = s_mean, inv = s_inv;
    float4 gg = *reinterpret_cast<const float4*>(g  + c0);
    float4 bb = *reinterpret_cast<const float4*>(be + c0);
    float o0 = (v0 - mean) * inv * gg.x + bb.x;
    float o1 = (v1 - mean) * inv * gg.y + bb.y;
    float o2 = (v2 - mean) * inv * gg.z + bb.z;
    float o3 = (v3 - mean) * inv * gg.w + bb.w;
    *reinterpret_cast<float4*>(out + (size_t)row * D_MODEL + c0) =
        make_float4(o0, o1, o2, o3);
    if (PACK) {
        uint32_t h0, l0, h1, l1;
        split_pack(o0, o1, h0, l0);
        split_pack(o2, o3, h1, l1);
        *reinterpret_cast<uint2*>(Ohi + (size_t)row * (D_MODEL/2) + tid*2) = make_uint2(h0, h1);
        *reinterpret_cast<uint2*>(Olo + (size_t)row * (D_MODEL/2) + tid*2) = make_uint2(l0, l1);
    }
}

// ---------------- launch -----------------------------------------------------
extern "C" void kernel_launch(void* const* d_in, const int* in_sizes, int n_in,
                              void* d_out, int out_size)
{
    const float* src = (const float*)d_in[0];
    const float* wq  = (const float*)d_in[1];
    const float* bq  = (const float*)d_in[2];
    const float* wk  = (const float*)d_in[3];
    const float* bk  = (const float*)d_in[4];
    const float* wv  = (const float*)d_in[5];
    const float* bv  = (const float*)d_in[6];
    const float* g1  = (const float*)d_in[7];
    const float* be1 = (const float*)d_in[8];
    const float* w1  = (const float*)d_in[9];
    const float* b1  = (const float*)d_in[10];
    const float* w2  = (const float*)d_in[11];
    const float* b2  = (const float*)d_in[12];
    const float* g2  = (const float*)d_in[13];
    const float* be2 = (const float*)d_in[14];
    float* out = (float*)d_out;

    float *pq, *pk, *pv, *pctx, *px, *py;
    uint32_t *srcp_hi, *srcp_lo, *xp_hi, *xp_lo, *hp_hi, *hp_lo;
    uint32_t *wqp_hi, *wqp_lo, *wkp_hi, *wkp_lo, *wvp_hi, *wvp_lo;
    uint32_t *w1p_hi, *w1p_lo, *w2p_hi, *w2p_lo;
    cudaGetSymbolAddress((void**)&pq,   g_q);
    cudaGetSymbolAddress((void**)&pk,   g_k);
    cudaGetSymbolAddress((void**)&pv,   g_v);
    cudaGetSymbolAddress((void**)&pctx, g_ctx);
    cudaGetSymbolAddress((void**)&px,   g_x);
    cudaGetSymbolAddress((void**)&py,   g_y);
    cudaGetSymbolAddress((void**)&srcp_hi, g_srcp_hi);
    cudaGetSymbolAddress((void**)&srcp_lo, g_srcp_lo);
    cudaGetSymbolAddress((void**)&xp_hi,   g_xp_hi);
    cudaGetSymbolAddress((void**)&xp_lo,   g_xp_lo);
    cudaGetSymbolAddress((void**)&hp_hi,   g_hp_hi);
    cudaGetSymbolAddress((void**)&hp_lo,   g_hp_lo);
    cudaGetSymbolAddress((void**)&wqp_hi,  g_wqp_hi);
    cudaGetSymbolAddress((void**)&wqp_lo,  g_wqp_lo);
    cudaGetSymbolAddress((void**)&wkp_hi,  g_wkp_hi);
    cudaGetSymbolAddress((void**)&wkp_lo,  g_wkp_lo);
    cudaGetSymbolAddress((void**)&wvp_hi,  g_wvp_hi);
    cudaGetSymbolAddress((void**)&wvp_lo,  g_wvp_lo);
    cudaGetSymbolAddress((void**)&w1p_hi,  g_w1p_hi);
    cudaGetSymbolAddress((void**)&w1p_lo,  g_w1p_lo);
    cudaGetSymbolAddress((void**)&w2p_hi,  g_w2p_hi);
    cudaGetSymbolAddress((void**)&w2p_lo,  g_w2p_lo);

    cudaFuncSetAttribute(gemm_bf16_kernel<false,false>,
                         cudaFuncAttributeMaxDynamicSharedMemorySize, GEMM_SMEM);
    cudaFuncSetAttribute(gemm_bf16_kernel<true,true>,
                         cudaFuncAttributeMaxDynamicSharedMemorySize, GEMM_SMEM);
    cudaFuncSetAttribute(flash_attn_kernel,
                         cudaFuncAttributeMaxDynamicSharedMemorySize, FA_SMEM);

    // pack inputs
    pack_act_kernel<<<TOKENS*D_MODEL/4/256, 256>>>(src, srcp_hi, srcp_lo,
                                                   TOKENS*D_MODEL/4);
    pack_weight_kernel<<<(D_MODEL/2)*(D_MODEL/4)/256, 256>>>(wq, wqp_hi, wqp_lo,
                                                             D_MODEL/2, D_MODEL);
    pack_weight_kernel<<<(D_MODEL/2)*(D_MODEL/4)/256, 256>>>(wk, wkp_hi, wkp_lo,
                                                             D_MODEL/2, D_MODEL);
    pack_weight_kernel<<<(D_MODEL/2)*(D_MODEL/4)/256, 256>>>(wv, wvp_hi, wvp_lo,
                                                             D_MODEL/2, D_MODEL);
    pack_weight_kernel<<<(D_MODEL/2)*(FEED/4)/256, 256>>>(w1, w1p_hi, w1p_lo,
                                                          D_MODEL/2, FEED);
    pack_weight_kernel<<<(FEED/2)*(D_MODEL/4)/256, 256>>>(w2, w2p_hi, w2p_lo,
                                                          FEED/2, D_MODEL);

    // QKV projections
    gemm_bf16_kernel<false,false><<<dim3(D_MODEL/128, TOKENS/128), 256, GEMM_SMEM>>>(
        srcp_hi, srcp_lo, wqp_hi, wqp_lo, bq, pq, nullptr, nullptr,
        TOKENS, D_MODEL, D_MODEL);
    gemm_bf16_kernel<false,false><<<dim3(D_MODEL/128, TOKENS/128), 256, GEMM_SMEM>>>(
        srcp_hi, srcp_lo, wkp_hi, wkp_lo, bk, pk, nullptr, nullptr,
        TOKENS, D_MODEL, D_MODEL);
    gemm_bf16_kernel<false,false><<<dim3(D_MODEL/128, TOKENS/128), 256, GEMM_SMEM>>>(
        srcp_hi, srcp_lo, wvp_hi, wvp_lo, bv, pv, nullptr, nullptr,
        TOKENS, D_MODEL, D_MODEL);

    // fused flash attention
    flash_attn_kernel<<<dim3(BH, SEQ/128), 256, FA_SMEM>>>(pq, pk, pv, pctx);

    // residual + LN1 (emit packed x for FFN1)
    add_ln_kernel<true><<<TOKENS, 256>>>(pctx, src, g1, be1, px, xp_hi, xp_lo);

    // FFN1: relu, packed output only (no fp32 h)
    gemm_bf16_kernel<true,true><<<dim3(FEED/128, TOKENS/128), 256, GEMM_SMEM>>>(
        xp_hi, xp_lo, w1p_hi, w1p_lo, b1, nullptr, hp_hi, hp_lo,
        TOKENS, FEED, D_MODEL);
    // FFN2
    gemm_bf16_kernel<false,false><<<dim3(D_MODEL/128, TOKENS/128), 256, GEMM_SMEM>>>(
        hp_hi, hp_lo, w2p_hi, w2p_lo, b2, py, nullptr, nullptr,
        TOKENS, D_MODEL, FEED);

    // residual + LN2 -> output
    add_ln_kernel<false><<<TOKENS, 256>>>(py, px, g2, be2, out, nullptr, nullptr);
}

// round 8
// speedup vs baseline: 2.3936x; 1.1157x over previous
#include <cuda_runtime.h>
#include <cuda_bf16.h>
#include <math.h>
#include <stdint.h>

#define D_MODEL 1024
#define FEED    4096
#define HEADS   16
#define DK      64
#define SEQ     512
#define BATCH   8
#define TOKENS  (BATCH*SEQ)    // 4096
#define BH      (BATCH*HEADS)  // 128

// ---------------- scratch (no allocations allowed) ----------------
__device__ float g_v  [TOKENS*(size_t)D_MODEL];
__device__ float g_ctx[TOKENS*(size_t)D_MODEL];
__device__ float g_x  [TOKENS*(size_t)D_MODEL];
__device__ float g_y  [TOKENS*(size_t)D_MODEL];
// packed bf16 hi/lo operands (k-pair packed: u32 = [bf16(k+1)<<16 | bf16(k)])
__device__ uint32_t g_srcp_hi[TOKENS*(size_t)(D_MODEL/2)];
__device__ uint32_t g_srcp_lo[TOKENS*(size_t)(D_MODEL/2)];
__device__ uint32_t g_qp_hi  [TOKENS*(size_t)(D_MODEL/2)];
__device__ uint32_t g_qp_lo  [TOKENS*(size_t)(D_MODEL/2)];
__device__ uint32_t g_kp_hi  [TOKENS*(size_t)(D_MODEL/2)];
__device__ uint32_t g_kp_lo  [TOKENS*(size_t)(D_MODEL/2)];
__device__ uint32_t g_xp_hi  [TOKENS*(size_t)(D_MODEL/2)];
__device__ uint32_t g_xp_lo  [TOKENS*(size_t)(D_MODEL/2)];
__device__ uint32_t g_hp_hi  [TOKENS*(size_t)(FEED/2)];
__device__ uint32_t g_hp_lo  [TOKENS*(size_t)(FEED/2)];
__device__ uint32_t g_wqp_hi [(size_t)(D_MODEL/2)*D_MODEL];
__device__ uint32_t g_wqp_lo [(size_t)(D_MODEL/2)*D_MODEL];
__device__ uint32_t g_wkp_hi [(size_t)(D_MODEL/2)*D_MODEL];
__device__ uint32_t g_wkp_lo [(size_t)(D_MODEL/2)*D_MODEL];
__device__ uint32_t g_wvp_hi [(size_t)(D_MODEL/2)*D_MODEL];
__device__ uint32_t g_wvp_lo [(size_t)(D_MODEL/2)*D_MODEL];
__device__ uint32_t g_w1p_hi [(size_t)(D_MODEL/2)*FEED];
__device__ uint32_t g_w1p_lo [(size_t)(D_MODEL/2)*FEED];
__device__ uint32_t g_w2p_hi [(size_t)(FEED/2)*D_MODEL];
__device__ uint32_t g_w2p_lo [(size_t)(FEED/2)*D_MODEL];

// ======================= helpers =======================
#define CP_ASYNC16(dst_u32, src) \
    asm volatile("cp.async.cg.shared.global [%0], [%1], 16;" \
                 :: "r"(dst_u32), "l"(src) : "memory")
#define CP_COMMIT()  asm volatile("cp.async.commit_group;" ::: "memory")
#define CP_WAIT2()   asm volatile("cp.async.wait_group 2;" ::: "memory")
#define CP_WAIT1()   asm volatile("cp.async.wait_group 1;" ::: "memory")
#define CP_WAIT0()   asm volatile("cp.async.wait_group 0;" ::: "memory")

#define MMA_BF16(d, a0,a1,a2,a3, b0,b1) \
    asm volatile("mma.sync.aligned.m16n8k16.row.col.f32.bf16.bf16.f32 " \
        "{%0,%1,%2,%3}, {%4,%5,%6,%7}, {%8,%9}, {%0,%1,%2,%3};" \
        : "+f"((d)[0]), "+f"((d)[1]), "+f"((d)[2]), "+f"((d)[3]) \
        : "r"(a0), "r"(a1), "r"(a2), "r"(a3), "r"(b0), "r"(b1))

// split-pack two consecutive-k fp32 values into bf16x2 hi and lo words
__device__ __forceinline__ void split_pack(float v0, float v1,
                                           uint32_t& hi, uint32_t& lo) {
    __nv_bfloat162 h = __floats2bfloat162_rn(v0, v1);
    float r0 = v0 - __bfloat162float(h.x);
    float r1 = v1 - __bfloat162float(h.y);
    __nv_bfloat162 l = __floats2bfloat162_rn(r0, r1);
    hi = *reinterpret_cast<uint32_t*>(&h);
    lo = *reinterpret_cast<uint32_t*>(&l);
}

// ======================= pack kernels =======================
__global__ __launch_bounds__(256) void pack_act_kernel(
    const float* __restrict__ X, uint32_t* __restrict__ Xhi,
    uint32_t* __restrict__ Xlo, int total4)
{
    int id = blockIdx.x * 256 + threadIdx.x;
    if (id >= total4) return;
    float4 v = *reinterpret_cast<const float4*>(X + (size_t)id * 4);
    uint32_t h0, l0, h1, l1;
    split_pack(v.x, v.y, h0, l0);
    split_pack(v.z, v.w, h1, l1);
    *reinterpret_cast<uint2*>(Xhi + (size_t)id * 2) = make_uint2(h0, h1);
    *reinterpret_cast<uint2*>(Xlo + (size_t)id * 2) = make_uint2(l0, l1);
}

__global__ __launch_bounds__(256) void pack_weight_kernel(
    const float* __restrict__ W, uint32_t* __restrict__ Bhi,
    uint32_t* __restrict__ Blo, int Kp, int N)
{
    int id = blockIdx.x * 256 + threadIdx.x;
    int n4cnt = N >> 2;
    if (id >= Kp * n4cnt) return;
    int kp = id / n4cnt, n4 = id % n4cnt;
    float4 w0 = *reinterpret_cast<const float4*>(W + (size_t)(2*kp)   * N + n4*4);
    float4 w1 = *reinterpret_cast<const float4*>(W + (size_t)(2*kp+1) * N + n4*4);
    uint32_t h[4], l[4];
    split_pack(w0.x, w1.x, h[0], l[0]);
    split_pack(w0.y, w1.y, h[1], l[1]);
    split_pack(w0.z, w1.z, h[2], l[2]);
    split_pack(w0.w, w1.w, h[3], l[3]);
    *reinterpret_cast<uint4*>(Bhi + (size_t)kp * N + n4*4) = make_uint4(h[0],h[1],h[2],h[3]);
    *reinterpret_cast<uint4*>(Blo + (size_t)kp * N + n4*4) = make_uint4(l[0],l[1],l[2],l[3]);
}

// ======================= bf16x3 GEMM =======================
// C[M,N] = A[M,K] @ W[K,N] + bias. CTA 128x256, warp tile 64x64, 8 warps,
// BK=32 (16 k-pairs), 3-stage cp.async pipeline.
#define AW 20     // u32 per A row per stage (16 + 4 pad)
#define BW 264    // u32 per B k-row per stage (256 + 8 pad)
#define ST_AHI 0
#define ST_ALO (128*AW*4)                 // 10240
#define ST_BHI (2*128*AW*4)               // 20480
#define ST_BLO (ST_BHI + 16*BW*4)         // 37376
#define ST_BYTES (ST_BHI + 2*16*BW*4)     // 54272
#define GEMM_SMEM (3*ST_BYTES)            // 162816

template<bool RELU, bool PACK_OUT>
__global__ __launch_bounds__(256, 1) void gemm_bf16_kernel(
    const uint32_t* __restrict__ Ahi, const uint32_t* __restrict__ Alo,
    const uint32_t* __restrict__ Bhi, const uint32_t* __restrict__ Blo,
    const float* __restrict__ bias, float* __restrict__ C,
    uint32_t* __restrict__ Ohi, uint32_t* __restrict__ Olo,
    int M, int N, int K)
{
    extern __shared__ char smem[];
    const uint32_t sbase = (uint32_t)__cvta_generic_to_shared(smem);

    const int tid = threadIdx.x;
    const int wid = tid >> 5;
    const int lane = tid & 31;
    const int gid = lane >> 2;
    const int tig = lane & 3;
    const int wy = wid >> 2;       // 0..1 -> rows wy*64
    const int wx = wid & 3;        // 0..3 -> cols wx*64

    const int bm = blockIdx.y * 128;
    const int bn = blockIdx.x * 256;
    const int Kp = K >> 1;
    const int nC = K >> 5;

    float acc[4][8][4];
#pragma unroll
    for (int i = 0; i < 4; i++)
#pragma unroll
        for (int j = 0; j < 8; j++)
#pragma unroll
            for (int r = 0; r < 4; r++) acc[i][j][r] = 0.f;

    const int ar[2] = { tid >> 2, (tid + 256) >> 2 };
    const int aq = tid & 3;
    const int bk[4] = { tid >> 6, (tid + 256) >> 6, (tid + 512) >> 6, (tid + 768) >> 6 };
    const int bq = tid & 63;

#define ISSUE(c) do { \
    const int _s = (c) % 3; \
    const int _kp0 = (c) << 4; \
    const uint32_t _sa = sbase + _s * ST_BYTES; \
    _Pragma("unroll") \
    for (int _i = 0; _i < 2; _i++) { \
        CP_ASYNC16(_sa + ST_AHI + ar[_i]*80 + aq*16, \
                   Ahi + (size_t)(bm + ar[_i])*Kp + _kp0 + aq*4); \
        CP_ASYNC16(_sa + ST_ALO + ar[_i]*80 + aq*16, \
                   Alo + (size_t)(bm + ar[_i])*Kp + _kp0 + aq*4); \
    } \
    _Pragma("unroll") \
    for (int _i = 0; _i < 4; _i++) { \
        CP_ASYNC16(_sa + ST_BHI + bk[_i]*1056 + bq*16, \
                   Bhi + (size_t)(_kp0 + bk[_i])*N + bn + bq*4); \
        CP_ASYNC16(_sa + ST_BLO + bk[_i]*1056 + bq*16, \
                   Blo + (size_t)(_kp0 + bk[_i])*N + bn + bq*4); \
    } \
    CP_COMMIT(); \
} while (0)

    ISSUE(0);
    ISSUE(1);

    for (int c = 0; c < nC; c++) {
        if (c + 2 < nC)      { ISSUE(c + 2); CP_WAIT2(); }
        else if (c + 1 < nC) { CP_WAIT1(); }
        else                 { CP_WAIT0(); }
        __syncthreads();

        const uint32_t* pAh = reinterpret_cast<const uint32_t*>(smem + (c % 3) * ST_BYTES);
        const uint32_t* pAl = pAh + 128*AW;
        const uint32_t* pBh = pAh + 2*128*AW;
        const uint32_t* pBl = pBh + 16*BW;

#pragma unroll
        for (int ks = 0; ks < 2; ks++) {
            const int kb = ks * 8;
            uint32_t Ah[4][4], Al[4][4];
#pragma unroll
            for (int mt = 0; mt < 4; mt++) {
                const int r0 = wy*64 + mt*16 + gid;
                Ah[mt][0] = pAh[(r0    )*AW + kb + tig    ];
                Ah[mt][1] = pAh[(r0 + 8)*AW + kb + tig    ];
                Ah[mt][2] = pAh[(r0    )*AW + kb + tig + 4];
                Ah[mt][3] = pAh[(r0 + 8)*AW + kb + tig + 4];
                Al[mt][0] = pAl[(r0    )*AW + kb + tig    ];
                Al[mt][1] = pAl[(r0 + 8)*AW + kb + tig    ];
                Al[mt][2] = pAl[(r0    )*AW + kb + tig + 4];
                Al[mt][3] = pAl[(r0 + 8)*AW + kb + tig + 4];
            }
#pragma unroll
            for (int nt = 0; nt < 8; nt++) {
                const int col = wx*64 + nt*8 + gid;
                uint32_t bh0 = pBh[(kb + tig    )*BW + col];
                uint32_t bh1 = pBh[(kb + tig + 4)*BW + col];
                uint32_t bl0 = pBl[(kb + tig    )*BW + col];
                uint32_t bl1 = pBl[(kb + tig + 4)*BW + col];
#pragma unroll
                for (int mt = 0; mt < 4; mt++) {
                    MMA_BF16(acc[mt][nt], Ah[mt][0], Ah[mt][1], Ah[mt][2], Ah[mt][3],
                             bh0, bh1);
                    MMA_BF16(acc[mt][nt], Al[mt][0], Al[mt][1], Al[mt][2], Al[mt][3],
                             bh0, bh1);
                    MMA_BF16(acc[mt][nt], Ah[mt][0], Ah[mt][1], Ah[mt][2], Ah[mt][3],
                             bl0, bl1);
                }
            }
        }
        __syncthreads();
    }

    // epilogue
    const int Np = N >> 1;
#pragma unroll
    for (int nt = 0; nt < 8; nt++) {
        const int cc = bn + wx*64 + nt*8 + tig*2;
        const float b0 = bias[cc], b1 = bias[cc + 1];
#pragma unroll
        for (int mt = 0; mt < 4; mt++) {
            const int r0 = bm + wy*64 + mt*16 + gid;
            float v0 = acc[mt][nt][0] + b0;
            float v1 = acc[mt][nt][1] + b1;
            float v2 = acc[mt][nt][2] + b0;
            float v3 = acc[mt][nt][3] + b1;
            if (RELU) {
                v0 = fmaxf(v0, 0.f); v1 = fmaxf(v1, 0.f);
                v2 = fmaxf(v2, 0.f); v3 = fmaxf(v3, 0.f);
            }
            if (PACK_OUT) {
                uint32_t h, l;
                split_pack(v0, v1, h, l);
                Ohi[(size_t)r0 * Np + (cc >> 1)] = h;
                Olo[(size_t)r0 * Np + (cc >> 1)] = l;
                split_pack(v2, v3, h, l);
                Ohi[(size_t)(r0 + 8) * Np + (cc >> 1)] = h;
                Olo[(size_t)(r0 + 8) * Np + (cc >> 1)] = l;
            } else {
                *reinterpret_cast<float2*>(C + (size_t)r0 * N + cc)       = make_float2(v0, v1);
                *reinterpret_cast<float2*>(C + (size_t)(r0 + 8) * N + cc) = make_float2(v2, v3);
            }
        }
    }
#undef ISSUE
}

// ======================= fused flash attention (bf16x3) ====================
// One CTA per (bh, 128-row q tile). 256 threads, 8 warps.
// Q,K pre-split packed along dk; V transpose-packed in-kernel; P packed from
// MMA accumulators during register softmax.
#define QW   36   // u32 stride for Q/K packed rows (32 + 4)
#define VtW  65   // u32 stride for Vt rows (64 + 1)
#define PsW  66   // u32 stride for P rows (64 + 2)
#define FQH  0
#define FQL  (FQH + 128*QW*4)        // 18432
#define FKH  (FQL + 128*QW*4)        // 36864
#define FKL  (FKH + 128*QW*4)        // 55296
#define FVH  (FKL + 128*QW*4)        // 73728
#define FVL  (FVH + 64*VtW*4)        // 90368
#define FPH  (FVL + 64*VtW*4)        // 107008
#define FPL  (FPH + 128*PsW*4)       // 140800
#define FMS  (FPL + 128*PsW*4)       // 174592
#define FLS  (FMS + 128*4)
#define FALS (FLS + 128*4)
#define FRED (FALS + 128*4)
#define FA_SMEM (FRED + 4*128*4)     // 178176

__global__ __launch_bounds__(256, 1) void flash_attn_kernel(
    const uint32_t* __restrict__ qh_g, const uint32_t* __restrict__ ql_g,
    const uint32_t* __restrict__ kh_g, const uint32_t* __restrict__ kl_g,
    const float* __restrict__ v, float* __restrict__ ctx)
{
    extern __shared__ char smem[];
    uint32_t* QsH = reinterpret_cast<uint32_t*>(smem + FQH);
    uint32_t* QsL = reinterpret_cast<uint32_t*>(smem + FQL);
    uint32_t* KsH = reinterpret_cast<uint32_t*>(smem + FKH);
    uint32_t* KsL = reinterpret_cast<uint32_t*>(smem + FKL);
    uint32_t* VtH = reinterpret_cast<uint32_t*>(smem + FVH);
    uint32_t* VtL = reinterpret_cast<uint32_t*>(smem + FVL);
    uint32_t* PsH = reinterpret_cast<uint32_t*>(smem + FPH);
    uint32_t* PsL = reinterpret_cast<uint32_t*>(smem + FPL);
    float* m_s  = reinterpret_cast<float*>(smem + FMS);
    float* l_s  = reinterpret_cast<float*>(smem + FLS);
    float* al_s = reinterpret_cast<float*>(smem + FALS);
    float* red  = reinterpret_cast<float*>(smem + FRED);

    const int tid = threadIdx.x;
    const int wid = tid >> 5;
    const int lane = tid & 31;
    const int gid = lane >> 2;
    const int tig = lane & 3;

    const int bh = blockIdx.x;
    const int b  = bh >> 4, h = bh & 15;
    const int q0 = blockIdx.y * 128;

    // load Q packed tile [128 x 32 words]
    {
        const uint32_t* qh = qh_g + (size_t)(b*SEQ + q0) * (D_MODEL/2) + h*32;
        const uint32_t* ql = ql_g + (size_t)(b*SEQ + q0) * (D_MODEL/2) + h*32;
#pragma unroll
        for (int i = 0; i < 4; i++) {
            int idx = tid + i * 256;
            int row = idx >> 3, qq = idx & 7;
            *reinterpret_cast<uint4*>(QsH + row*QW + qq*4) =
                *reinterpret_cast<const uint4*>(qh + (size_t)row * (D_MODEL/2) + qq*4);
            *reinterpret_cast<uint4*>(QsL + row*QW + qq*4) =
                *reinterpret_cast<const uint4*>(ql + (size_t)row * (D_MODEL/2) + qq*4);
        }
    }
    if (tid < 128) { m_s[tid] = -INFINITY; l_s[tid] = 0.f; }

    // O accumulators: warp tile 32x32 over 128x64
    const int wy2 = wid >> 1;      // 0..3
    const int wx2 = wid & 1;       // 0..1
    float acc_o[2][4][4];
#pragma unroll
    for (int mt = 0; mt < 2; mt++)
#pragma unroll
        for (int nt = 0; nt < 4; nt++)
#pragma unroll
            for (int r = 0; r < 4; r++) acc_o[mt][nt][r] = 0.f;

    // S warp tile 64x32 over 128x128
    const int wy = wid >> 2;       // 0..1
    const int wx = wid & 3;        // 0..3

    for (int kt = 0; kt < 4; kt++) {
        __syncthreads();
        const int s0 = kt * 128;
        // K packed tile
        {
            const uint32_t* kh = kh_g + (size_t)(b*SEQ + s0) * (D_MODEL/2) + h*32;
            const uint32_t* kl = kl_g + (size_t)(b*SEQ + s0) * (D_MODEL/2) + h*32;
#pragma unroll
            for (int i = 0; i < 4; i++) {
                int idx = tid + i * 256;
                int row = idx >> 3, qq = idx & 7;
                *reinterpret_cast<uint4*>(KsH + row*QW + qq*4) =
                    *reinterpret_cast<const uint4*>(kh + (size_t)row * (D_MODEL/2) + qq*4);
                *reinterpret_cast<uint4*>(KsL + row*QW + qq*4) =
                    *reinterpret_cast<const uint4*>(kl + (size_t)row * (D_MODEL/2) + qq*4);
            }
        }
        // V transpose-pack: Vt[dk][sp] = pack(V[2sp][dk], V[2sp+1][dk])
        {
            const float* vg = v + (size_t)(b*SEQ + s0) * D_MODEL + h*DK;
#pragma unroll
            for (int i = 0; i < 4; i++) {
                int idx = tid + i * 256;
                int sp = idx >> 4, dk4 = idx & 15;
                float4 r0v = *reinterpret_cast<const float4*>(vg + (size_t)(2*sp  ) * D_MODEL + dk4*4);
                float4 r1v = *reinterpret_cast<const float4*>(vg + (size_t)(2*sp+1) * D_MODEL + dk4*4);
                uint32_t hh, ll;
                split_pack(r0v.x, r1v.x, hh, ll);
                VtH[(dk4*4+0)*VtW + sp] = hh; VtL[(dk4*4+0)*VtW + sp] = ll;
                split_pack(r0v.y, r1v.y, hh, ll);
                VtH[(dk4*4+1)*VtW + sp] = hh; VtL[(dk4*4+1)*VtW + sp] = ll;
                split_pack(r0v.z, r1v.z, hh, ll);
                VtH[(dk4*4+2)*VtW + sp] = hh; VtL[(dk4*4+2)*VtW + sp] = ll;
                split_pack(r0v.w, r1v.w, hh, ll);
                VtH[(dk4*4+3)*VtW + sp] = hh; VtL[(dk4*4+3)*VtW + sp] = ll;
            }
        }
        __syncthreads();

        // ---- S = Q @ K^T (128x128, k=64 -> 4 k16 steps) ----
        float s_acc[4][4][4];
#pragma unroll
        for (int i = 0; i < 4; i++)
#pragma unroll
            for (int j = 0; j < 4; j++)
#pragma unroll
                for (int r = 0; r < 4; r++) s_acc[i][j][r] = 0.f;

#pragma unroll
        for (int ks = 0; ks < 4; ks++) {
            const int kb = ks * 8;
            uint32_t Ah[4][4], Al[4][4];
#pragma unroll
            for (int mt = 0; mt < 4; mt++) {
                const int r0 = wy*64 + mt*16 + gid;
                Ah[mt][0] = QsH[(r0    )*QW + kb + tig    ];
                Ah[mt][1] = QsH[(r0 + 8)*QW + kb + tig    ];
                Ah[mt][2] = QsH[(r0    )*QW + kb + tig + 4];
                Ah[mt][3] = QsH[(r0 + 8)*QW + kb + tig + 4];
                Al[mt][0] = QsL[(r0    )*QW + kb + tig    ];
                Al[mt][1] = QsL[(r0 + 8)*QW + kb + tig    ];
                Al[mt][2] = QsL[(r0    )*QW + kb + tig + 4];
                Al[mt][3] = QsL[(r0 + 8)*QW + kb + tig + 4];
            }
#pragma unroll
            for (int nt = 0; nt < 4; nt++) {
                const int col = wx*32 + nt*8 + gid;
                uint32_t bh0 = KsH[col*QW + kb + tig    ];
                uint32_t bh1 = KsH[col*QW + kb + tig + 4];
                uint32_t bl0 = KsL[col*QW + kb + tig    ];
                uint32_t bl1 = KsL[col*QW + kb + tig + 4];
#pragma unroll
                for (int mt = 0; mt < 4; mt++) {
                    MMA_BF16(s_acc[mt][nt], Ah[mt][0], Ah[mt][1], Ah[mt][2], Ah[mt][3],
                             bh0, bh1);
                    MMA_BF16(s_acc[mt][nt], Al[mt][0], Al[mt][1], Al[mt][2], Al[mt][3],
                             bh0, bh1);
                    MMA_BF16(s_acc[mt][nt], Ah[mt][0], Ah[mt][1], Ah[mt][2], Ah[mt][3],
                             bl0, bl1);
                }
            }
        }

        // scale + per-warp row max
#pragma unroll
        for (int mt = 0; mt < 4; mt++) {
            float rlo = -INFINITY, rhi = -INFINITY;
#pragma unroll
            for (int nt = 0; nt < 4; nt++) {
                s_acc[mt][nt][0] *= 0.125f; s_acc[mt][nt][1] *= 0.125f;
                s_acc[mt][nt][2] *= 0.125f; s_acc[mt][nt][3] *= 0.125f;
                rlo = fmaxf(rlo, fmaxf(s_acc[mt][nt][0], s_acc[mt][nt][1]));
                rhi = fmaxf(rhi, fmaxf(s_acc[mt][nt][2], s_acc[mt][nt][3]));
            }
            rlo = fmaxf(rlo, __shfl_xor_sync(~0u, rlo, 1));
            rlo = fmaxf(rlo, __shfl_xor_sync(~0u, rlo, 2));
            rhi = fmaxf(rhi, __shfl_xor_sync(~0u, rhi, 1));
            rhi = fmaxf(rhi, __shfl_xor_sync(~0u, rhi, 2));
            if (tig == 0) {
                const int r0 = wy*64 + mt*16 + gid;
                red[wx*128 + r0]     = rlo;
                red[wx*128 + r0 + 8] = rhi;
            }
        }
        __syncthreads();
        if (tid < 128) {
            float mo = m_s[tid];
            float mn = fmaxf(fmaxf(red[tid], red[128 + tid]),
                             fmaxf(red[256 + tid], red[384 + tid]));
            mn = fmaxf(mo, mn);
            al_s[tid] = __expf(mo - mn);
            m_s[tid]  = mn;
        }
        __syncthreads();

        // exp + pack P + partial row sums
#pragma unroll
        for (int mt = 0; mt < 4; mt++) {
            const int rlo = wy*64 + mt*16 + gid;
            const float mlo = m_s[rlo];
            const float mhi = m_s[rlo + 8];
            float slo = 0.f, shi = 0.f;
#pragma unroll
            for (int nt = 0; nt < 4; nt++) {
                float d0 = __expf(s_acc[mt][nt][0] - mlo);
                float d1 = __expf(s_acc[mt][nt][1] - mlo);
                float d2 = __expf(s_acc[mt][nt][2] - mhi);
                float d3 = __expf(s_acc[mt][nt][3] - mhi);
                slo += d0 + d1; shi += d2 + d3;
                const int word = wx*16 + nt*4 + tig;
                uint32_t hh, ll;
                split_pack(d0, d1, hh, ll);
                PsH[rlo*PsW + word] = hh; PsL[rlo*PsW + word] = ll;
                split_pack(d2, d3, hh, ll);
                PsH[(rlo+8)*PsW + word] = hh; PsL[(rlo+8)*PsW + word] = ll;
            }
            slo += __shfl_xor_sync(~0u, slo, 1);
            slo += __shfl_xor_sync(~0u, slo, 2);
            shi += __shfl_xor_sync(~0u, shi, 1);
            shi += __shfl_xor_sync(~0u, shi, 2);
            if (tig == 0) {
                red[wx*128 + rlo]     = slo;
                red[wx*128 + rlo + 8] = shi;
            }
        }
        // rescale O by alpha
#pragma unroll
        for (int mt = 0; mt < 2; mt++) {
            const int r0 = wy2*32 + mt*16 + gid;
            const float aL = al_s[r0];
            const float aH = al_s[r0 + 8];
#pragma unroll
            for (int nt = 0; nt < 4; nt++) {
                acc_o[mt][nt][0] *= aL; acc_o[mt][nt][1] *= aL;
                acc_o[mt][nt][2] *= aH; acc_o[mt][nt][3] *= aH;
            }
        }
        __syncthreads();
        if (tid < 128) {
            l_s[tid] = al_s[tid] * l_s[tid] +
                       (red[tid] + red[128 + tid] + red[256 + tid] + red[384 + tid]);
        }

        // ---- O += P @ V  (128x64, k=128 -> 8 k16 steps) ----
#pragma unroll
        for (int ks = 0; ks < 8; ks++) {
            const int kb = ks * 8;
            uint32_t Ph[2][4], Pl[2][4];
#pragma unroll
            for (int mt = 0; mt < 2; mt++) {
                const int r0 = wy2*32 + mt*16 + gid;
                Ph[mt][0] = PsH[(r0    )*PsW + kb + tig    ];
                Ph[mt][1] = PsH[(r0 + 8)*PsW + kb + tig    ];
                Ph[mt][2] = PsH[(r0    )*PsW + kb + tig + 4];
                Ph[mt][3] = PsH[(r0 + 8)*PsW + kb + tig + 4];
                Pl[mt][0] = PsL[(r0    )*PsW + kb + tig    ];
                Pl[mt][1] = PsL[(r0 + 8)*PsW + kb + tig    ];
                Pl[mt][2] = PsL[(r0    )*PsW + kb + tig + 4];
                Pl[mt][3] = PsL[(r0 + 8)*PsW + kb + tig + 4];
            }
#pragma unroll
            for (int nt = 0; nt < 4; nt++) {
                const int dc = wx2*32 + nt*8 + gid;
                uint32_t vh0 = VtH[dc*VtW + kb + tig    ];
                uint32_t vh1 = VtH[dc*VtW + kb + tig + 4];
                uint32_t vl0 = VtL[dc*VtW + kb + tig    ];
                uint32_t vl1 = VtL[dc*VtW + kb + tig + 4];
#pragma unroll
                for (int mt = 0; mt < 2; mt++) {
                    MMA_BF16(acc_o[mt][nt], Ph[mt][0], Ph[mt][1], Ph[mt][2], Ph[mt][3],
                             vh0, vh1);
                    MMA_BF16(acc_o[mt][nt], Pl[mt][0], Pl[mt][1], Pl[mt][2], Pl[mt][3],
                             vh0, vh1);
                    MMA_BF16(acc_o[mt][nt], Ph[mt][0], Ph[mt][1], Ph[mt][2], Ph[mt][3],
                             vl0, vl1);
                }
            }
        }
    }

    __syncthreads();
#pragma unroll
    for (int mt = 0; mt < 2; mt++) {
        const int r0 = wy2*32 + mt*16 + gid;
        const float iL = 1.f / l_s[r0];
        const float iH = 1.f / l_s[r0 + 8];
#pragma unroll
        for (int nt = 0; nt < 4; nt++) {
            const int dc = h*DK + wx2*32 + nt*8 + tig*2;
            const size_t rowL = (size_t)(b*SEQ + q0 + r0);
            *reinterpret_cast<float2*>(ctx + rowL * D_MODEL + dc) =
                make_float2(acc_o[mt][nt][0]*iL, acc_o[mt][nt][1]*iL);
            *reinterpret_cast<float2*>(ctx + (rowL+8) * D_MODEL + dc) =
                make_float2(acc_o[mt][nt][2]*iH, acc_o[mt][nt][3]*iH);
        }
    }
}

// ---------------- fused residual-add + LayerNorm (+ optional bf16 packing) ---
template<bool PACK>
__global__ __launch_bounds__(256) void add_ln_kernel(
    const float* __restrict__ a, const float* __restrict__ r,
    const float* __restrict__ g, const float* __restrict__ be,
    float* __restrict__ out, uint32_t* __restrict__ Ohi,
    uint32_t* __restrict__ Olo)
{
    __shared__ float reds[8], reds2[8];
    __shared__ float s_mean, s_inv;
    const int row = blockIdx.x;
    const int tid = threadIdx.x;
    const int c0 = tid * 4;
    float4 va = *reinterpret_cast<const float4*>(a + (size_t)row * D_MODEL + c0);
    float4 vr = *reinterpret_cast<const float4*>(r + (size_t)row * D_MODEL + c0);
    float v0 = va.x + vr.x, v1 = va.y + vr.y, v2 = va.z + vr.z, v3 = va.w + vr.w;
    float s  = v0 + v1 + v2 + v3;
    float s2 = v0*v0 + v1*v1 + v2*v2 + v3*v3;
#pragma unroll
    for (int o = 16; o > 0; o >>= 1) {
        s  += __shfl_xor_sync(~0u, s,  o);
        s2 += __shfl_xor_sync(~0u, s2, o);
    }
    if ((tid & 31) == 0) { reds[tid >> 5] = s; reds2[tid >> 5] = s2; }
    __syncthreads();
    if (tid < 32) {
        float v  = (tid < 8) ? reds[tid]  : 0.f;
        float vv = (tid < 8) ? reds2[tid] : 0.f;
#pragma unroll
        for (int o = 4; o > 0; o >>= 1) {
            v  += __shfl_xor_sync(~0u, v,  o);
            vv += __shfl_xor_sync(~0u, vv, o);
        }
        if (tid == 0) {
            float mean = v * (1.f / D_MODEL);
            float var  = vv * (1.f / D_MODEL) - mean * mean;
            s_mean = mean;
            s_inv  = rsqrtf(var + 1e-5f);
        }
    }
    __syncthreads();
    const float mean = s_mean, inv = s_inv;
    float4 gg = *reinterpret_cast<const float4*>(g  + c0);
    float4 bb = *reinterpret_cast<const float4*>(be + c0);
    float o0 = (v0 - mean) * inv * gg.x + bb.x;
    float o1 = (v1 - mean) * inv * gg.y + bb.y;
    float o2 = (v2 - mean) * inv * gg.z + bb.z;
    float o3 = (v3 - mean) * inv * gg.w + bb.w;
    *reinterpret_cast<float4*>(out + (size_t)row * D_MODEL + c0) =
        make_float4(o0, o1, o2, o3);
    if (PACK) {
        uint32_t h0, l0, h1, l1;
        split_pack(o0, o1, h0, l0);
        split_pack(o2, o3, h1, l1);
        *reinterpret_cast<uint2*>(Ohi + (size_t)row * (D_MODEL/2) + tid*2) = make_uint2(h0, h1);
        *reinterpret_cast<uint2*>(Olo + (size_t)row * (D_MODEL/2) + tid*2) = make_uint2(l0, l1);
    }
}

// ---------------- launch -----------------------------------------------------
extern "C" void kernel_launch(void* const* d_in, const int* in_sizes, int n_in,
                              void* d_out, int out_size)
{
    const float* src = (const float*)d_in[0];
    const float* wq  = (const float*)d_in[1];
    const float* bq  = (const float*)d_in[2];
    const float* wk  = (const float*)d_in[3];
    const float* bk  = (const float*)d_in[4];
    const float* wv  = (const float*)d_in[5];
    const float* bv  = (const float*)d_in[6];
    const float* g1  = (const float*)d_in[7];
    const float* be1 = (const float*)d_in[8];
    const float* w1  = (const float*)d_in[9];
    const float* b1  = (const float*)d_in[10];
    const float* w2  = (const float*)d_in[11];
    const float* b2  = (const float*)d_in[12];
    const float* g2  = (const float*)d_in[13];
    const float* be2 = (const float*)d_in[14];
    float* out = (float*)d_out;

    float *pv, *pctx, *px, *py;
    uint32_t *srcp_hi, *srcp_lo, *qp_hi, *qp_lo, *kp_hi, *kp_lo;
    uint32_t *xp_hi, *xp_lo, *hp_hi, *hp_lo;
    uint32_t *wqp_hi, *wqp_lo, *wkp_hi, *wkp_lo, *wvp_hi, *wvp_lo;
    uint32_t *w1p_hi, *w1p_lo, *w2p_hi, *w2p_lo;
    cudaGetSymbolAddress((void**)&pv,   g_v);
    cudaGetSymbolAddress((void**)&pctx, g_ctx);
    cudaGetSymbolAddress((void**)&px,   g_x);
    cudaGetSymbolAddress((void**)&py,   g_y);
    cudaGetSymbolAddress((void**)&srcp_hi, g_srcp_hi);
    cudaGetSymbolAddress((void**)&srcp_lo, g_srcp_lo);
    cudaGetSymbolAddress((void**)&qp_hi,   g_qp_hi);
    cudaGetSymbolAddress((void**)&qp_lo,   g_qp_lo);
    cudaGetSymbolAddress((void**)&kp_hi,   g_kp_hi);
    cudaGetSymbolAddress((void**)&kp_lo,   g_kp_lo);
    cudaGetSymbolAddress((void**)&xp_hi,   g_xp_hi);
    cudaGetSymbolAddress((void**)&xp_lo,   g_xp_lo);
    cudaGetSymbolAddress((void**)&hp_hi,   g_hp_hi);
    cudaGetSymbolAddress((void**)&hp_lo,   g_hp_lo);
    cudaGetSymbolAddress((void**)&wqp_hi,  g_wqp_hi);
    cudaGetSymbolAddress((void**)&wqp_lo,  g_wqp_lo);
    cudaGetSymbolAddress((void**)&wkp_hi,  g_wkp_hi);
    cudaGetSymbolAddress((void**)&wkp_lo,  g_wkp_lo);
    cudaGetSymbolAddress((void**)&wvp_hi,  g_wvp_hi);
    cudaGetSymbolAddress((void**)&wvp_lo,  g_wvp_lo);
    cudaGetSymbolAddress((void**)&w1p_hi,  g_w1p_hi);
    cudaGetSymbolAddress((void**)&w1p_lo,  g_w1p_lo);
    cudaGetSymbolAddress((void**)&w2p_hi,  g_w2p_hi);
    cudaGetSymbolAddress((void**)&w2p_lo,  g_w2p_lo);

    cudaFuncSetAttribute(gemm_bf16_kernel<false,false>,
                         cudaFuncAttributeMaxDynamicSharedMemorySize, GEMM_SMEM);
    cudaFuncSetAttribute(gemm_bf16_kernel<false,true>,
                         cudaFuncAttributeMaxDynamicSharedMemorySize, GEMM_SMEM);
    cudaFuncSetAttribute(gemm_bf16_kernel<true,true>,
                         cudaFuncAttributeMaxDynamicSharedMemorySize, GEMM_SMEM);
    cudaFuncSetAttribute(flash_attn_kernel,
                         cudaFuncAttributeMaxDynamicSharedMemorySize, FA_SMEM);

    // pack inputs
    pack_act_kernel<<<TOKENS*D_MODEL/4/256, 256>>>(src, srcp_hi, srcp_lo,
                                                   TOKENS*D_MODEL/4);
    pack_weight_kernel<<<(D_MODEL/2)*(D_MODEL/4)/256, 256>>>(wq, wqp_hi, wqp_lo,
                                                             D_MODEL/2, D_MODEL);
    pack_weight_kernel<<<(D_MODEL/2)*(D_MODEL/4)/256, 256>>>(wk, wkp_hi, wkp_lo,
                                                             D_MODEL/2, D_MODEL);
    pack_weight_kernel<<<(D_MODEL/2)*(D_MODEL/4)/256, 256>>>(wv, wvp_hi, wvp_lo,
                                                             D_MODEL/2, D_MODEL);
    pack_weight_kernel<<<(D_MODEL/2)*(FEED/4)/256, 256>>>(w1, w1p_hi, w1p_lo,
                                                          D_MODEL/2, FEED);
    pack_weight_kernel<<<(FEED/2)*(D_MODEL/4)/256, 256>>>(w2, w2p_hi, w2p_lo,
                                                          FEED/2, D_MODEL);

    // QKV projections: Q,K emit packed bf16; V emits fp32
    gemm_bf16_kernel<false,true><<<dim3(D_MODEL/256, TOKENS/128), 256, GEMM_SMEM>>>(
        srcp_hi, srcp_lo, wqp_hi, wqp_lo, bq, nullptr, qp_hi, qp_lo,
        TOKENS, D_MODEL, D_MODEL);
    gemm_bf16_kernel<false,true><<<dim3(D_MODEL/256, TOKENS/128), 256, GEMM_SMEM>>>(
        srcp_hi, srcp_lo, wkp_hi, wkp_lo, bk, nullptr, kp_hi, kp_lo,
        TOKENS, D_MODEL, D_MODEL);
    gemm_bf16_kernel<false,false><<<dim3(D_MODEL/256, TOKENS/128), 256, GEMM_SMEM>>>(
        srcp_hi, srcp_lo, wvp_hi, wvp_lo, bv, pv, nullptr, nullptr,
        TOKENS, D_MODEL, D_MODEL);

    // fused flash attention (bf16x3)
    flash_attn_kernel<<<dim3(BH, SEQ/128), 256, FA_SMEM>>>(
        qp_hi, qp_lo, kp_hi, kp_lo, pv, pctx);

    // residual + LN1 (emit packed x for FFN1)
    add_ln_kernel<true><<<TOKENS, 256>>>(pctx, src, g1, be1, px, xp_hi, xp_lo);

    // FFN1: relu, packed output only
    gemm_bf16_kernel<true,true><<<dim3(FEED/256, TOKENS/128), 256, GEMM_SMEM>>>(
        xp_hi, xp_lo, w1p_hi, w1p_lo, b1, nullptr, hp_hi, hp_lo,
        TOKENS, FEED, D_MODEL);
    // FFN2
    gemm_bf16_kernel<false,false><<<dim3(D_MODEL/256, TOKENS/128), 256, GEMM_SMEM>>>(
        hp_hi, hp_lo, w2p_hi, w2p_lo, b2, py, nullptr, nullptr,
        TOKENS, D_MODEL, FEED);

    // residual + LN2 -> output
    add_ln_kernel<false><<<TOKENS, 256>>>(py, px, g2, be2, out, nullptr, nullptr);
}

// round 9
// speedup vs baseline: 2.4029x; 1.0039x over previous
#include <cuda_runtime.h>
#include <cuda_bf16.h>
#include <math.h>
#include <stdint.h>

#define D_MODEL 1024
#define FEED    4096
#define HEADS   16
#define DK      64
#define SEQ     512
#define BATCH   8
#define TOKENS  (BATCH*SEQ)    // 4096
#define BH      (BATCH*HEADS)  // 128

// ---------------- scratch (no allocations allowed) ----------------
__device__ float g_v  [TOKENS*(size_t)D_MODEL];
__device__ float g_ctx[TOKENS*(size_t)D_MODEL];
__device__ float g_x  [TOKENS*(size_t)D_MODEL];
__device__ float g_y  [TOKENS*(size_t)D_MODEL];
// packed bf16 hi/lo operands (k-pair packed: u32 = [bf16(k+1)<<16 | bf16(k)])
__device__ uint32_t g_srcp_hi[TOKENS*(size_t)(D_MODEL/2)];
__device__ uint32_t g_srcp_lo[TOKENS*(size_t)(D_MODEL/2)];
__device__ uint32_t g_qp_hi  [TOKENS*(size_t)(D_MODEL/2)];
__device__ uint32_t g_qp_lo  [TOKENS*(size_t)(D_MODEL/2)];
__device__ uint32_t g_kp_hi  [TOKENS*(size_t)(D_MODEL/2)];
__device__ uint32_t g_kp_lo  [TOKENS*(size_t)(D_MODEL/2)];
__device__ uint32_t g_xp_hi  [TOKENS*(size_t)(D_MODEL/2)];
__device__ uint32_t g_xp_lo  [TOKENS*(size_t)(D_MODEL/2)];
__device__ uint32_t g_hp_hi  [TOKENS*(size_t)(FEED/2)];
__device__ uint32_t g_hp_lo  [TOKENS*(size_t)(FEED/2)];
__device__ uint32_t g_wqp_hi [(size_t)(D_MODEL/2)*D_MODEL];
__device__ uint32_t g_wqp_lo [(size_t)(D_MODEL/2)*D_MODEL];
__device__ uint32_t g_wkp_hi [(size_t)(D_MODEL/2)*D_MODEL];
__device__ uint32_t g_wkp_lo [(size_t)(D_MODEL/2)*D_MODEL];
__device__ uint32_t g_wvp_hi [(size_t)(D_MODEL/2)*D_MODEL];
__device__ uint32_t g_wvp_lo [(size_t)(D_MODEL/2)*D_MODEL];
__device__ uint32_t g_w1p_hi [(size_t)(D_MODEL/2)*FEED];
__device__ uint32_t g_w1p_lo [(size_t)(D_MODEL/2)*FEED];
__device__ uint32_t g_w2p_hi [(size_t)(FEED/2)*D_MODEL];
__device__ uint32_t g_w2p_lo [(size_t)(FEED/2)*D_MODEL];

// ======================= helpers =======================
#define CP_ASYNC16(dst_u32, src) \
    asm volatile("cp.async.cg.shared.global [%0], [%1], 16;" \
                 :: "r"(dst_u32), "l"(src) : "memory")
#define CP_COMMIT()  asm volatile("cp.async.commit_group;" ::: "memory")
#define CP_WAIT2()   asm volatile("cp.async.wait_group 2;" ::: "memory")
#define CP_WAIT1()   asm volatile("cp.async.wait_group 1;" ::: "memory")
#define CP_WAIT0()   asm volatile("cp.async.wait_group 0;" ::: "memory")

#define MMA_BF16(d, a0,a1,a2,a3, b0,b1) \
    asm volatile("mma.sync.aligned.m16n8k16.row.col.f32.bf16.bf16.f32 " \
        "{%0,%1,%2,%3}, {%4,%5,%6,%7}, {%8,%9}, {%0,%1,%2,%3};" \
        : "+f"((d)[0]), "+f"((d)[1]), "+f"((d)[2]), "+f"((d)[3]) \
        : "r"(a0), "r"(a1), "r"(a2), "r"(a3), "r"(b0), "r"(b1))

// split-pack two consecutive-k fp32 values into bf16x2 hi and lo words
__device__ __forceinline__ void split_pack(float v0, float v1,
                                           uint32_t& hi, uint32_t& lo) {
    __nv_bfloat162 h = __floats2bfloat162_rn(v0, v1);
    float r0 = v0 - __bfloat162float(h.x);
    float r1 = v1 - __bfloat162float(h.y);
    __nv_bfloat162 l = __floats2bfloat162_rn(r0, r1);
    hi = *reinterpret_cast<uint32_t*>(&h);
    lo = *reinterpret_cast<uint32_t*>(&l);
}

// ======================= pack kernels =======================
__global__ __launch_bounds__(256) void pack_act_kernel(
    const float* __restrict__ X, uint32_t* __restrict__ Xhi,
    uint32_t* __restrict__ Xlo, int total4)
{
    int id = blockIdx.x * 256 + threadIdx.x;
    if (id >= total4) return;
    float4 v = *reinterpret_cast<const float4*>(X + (size_t)id * 4);
    uint32_t h0, l0, h1, l1;
    split_pack(v.x, v.y, h0, l0);
    split_pack(v.z, v.w, h1, l1);
    *reinterpret_cast<uint2*>(Xhi + (size_t)id * 2) = make_uint2(h0, h1);
    *reinterpret_cast<uint2*>(Xlo + (size_t)id * 2) = make_uint2(l0, l1);
}

__global__ __launch_bounds__(256) void pack_weight_kernel(
    const float* __restrict__ W, uint32_t* __restrict__ Bhi,
    uint32_t* __restrict__ Blo, int Kp, int N)
{
    int id = blockIdx.x * 256 + threadIdx.x;
    int n4cnt = N >> 2;
    if (id >= Kp * n4cnt) return;
    int kp = id / n4cnt, n4 = id % n4cnt;
    float4 w0 = *reinterpret_cast<const float4*>(W + (size_t)(2*kp)   * N + n4*4);
    float4 w1 = *reinterpret_cast<const float4*>(W + (size_t)(2*kp+1) * N + n4*4);
    uint32_t h[4], l[4];
    split_pack(w0.x, w1.x, h[0], l[0]);
    split_pack(w0.y, w1.y, h[1], l[1]);
    split_pack(w0.z, w1.z, h[2], l[2]);
    split_pack(w0.w, w1.w, h[3], l[3]);
    *reinterpret_cast<uint4*>(Bhi + (size_t)kp * N + n4*4) = make_uint4(h[0],h[1],h[2],h[3]);
    *reinterpret_cast<uint4*>(Blo + (size_t)kp * N + n4*4) = make_uint4(l[0],l[1],l[2],l[3]);
}

// ======================= bf16x3 GEMM =======================
// C[M,N] = A[M,K] @ W[K,N] + bias. CTA 128x256, warp tile 64x64, 8 warps,
// BK=32 (16 k-pairs), 3-stage cp.async pipeline.
#define AW 20     // u32 per A row per stage (16 + 4 pad)
#define BW 264    // u32 per B k-row per stage (256 + 8 pad)
#define ST_AHI 0
#define ST_ALO (128*AW*4)                 // 10240
#define ST_BHI (2*128*AW*4)               // 20480
#define ST_BLO (ST_BHI + 16*BW*4)         // 37376
#define ST_BYTES (ST_BHI + 2*16*BW*4)     // 54272
#define GEMM_SMEM (3*ST_BYTES)            // 162816

template<bool RELU, bool PACK_OUT>
__global__ __launch_bounds__(256, 1) void gemm_bf16_kernel(
    const uint32_t* __restrict__ Ahi, const uint32_t* __restrict__ Alo,
    const uint32_t* __restrict__ Bhi, const uint32_t* __restrict__ Blo,
    const float* __restrict__ bias, float* __restrict__ C,
    uint32_t* __restrict__ Ohi, uint32_t* __restrict__ Olo,
    int M, int N, int K)
{
    extern __shared__ char smem[];
    const uint32_t sbase = (uint32_t)__cvta_generic_to_shared(smem);

    const int tid = threadIdx.x;
    const int wid = tid >> 5;
    const int lane = tid & 31;
    const int gid = lane >> 2;
    const int tig = lane & 3;
    const int wy = wid >> 2;       // 0..1 -> rows wy*64
    const int wx = wid & 3;        // 0..3 -> cols wx*64

    const int bm = blockIdx.y * 128;
    const int bn = blockIdx.x * 256;
    const int Kp = K >> 1;
    const int nC = K >> 5;

    float acc[4][8][4];
#pragma unroll
    for (int i = 0; i < 4; i++)
#pragma unroll
        for (int j = 0; j < 8; j++)
#pragma unroll
            for (int r = 0; r < 4; r++) acc[i][j][r] = 0.f;

    const int ar[2] = { tid >> 2, (tid + 256) >> 2 };
    const int aq = tid & 3;
    const int bk[4] = { tid >> 6, (tid + 256) >> 6, (tid + 512) >> 6, (tid + 768) >> 6 };
    const int bq = tid & 63;

#define ISSUE(c) do { \
    const int _s = (c) % 3; \
    const int _kp0 = (c) << 4; \
    const uint32_t _sa = sbase + _s * ST_BYTES; \
    _Pragma("unroll") \
    for (int _i = 0; _i < 2; _i++) { \
        CP_ASYNC16(_sa + ST_AHI + ar[_i]*80 + aq*16, \
                   Ahi + (size_t)(bm + ar[_i])*Kp + _kp0 + aq*4); \
        CP_ASYNC16(_sa + ST_ALO + ar[_i]*80 + aq*16, \
                   Alo + (size_t)(bm + ar[_i])*Kp + _kp0 + aq*4); \
    } \
    _Pragma("unroll") \
    for (int _i = 0; _i < 4; _i++) { \
        CP_ASYNC16(_sa + ST_BHI + bk[_i]*1056 + bq*16, \
                   Bhi + (size_t)(_kp0 + bk[_i])*N + bn + bq*4); \
        CP_ASYNC16(_sa + ST_BLO + bk[_i]*1056 + bq*16, \
                   Blo + (size_t)(_kp0 + bk[_i])*N + bn + bq*4); \
    } \
    CP_COMMIT(); \
} while (0)

    ISSUE(0);
    ISSUE(1);

    for (int c = 0; c < nC; c++) {
        if (c + 2 < nC)      { ISSUE(c + 2); CP_WAIT2(); }
        else if (c + 1 < nC) { CP_WAIT1(); }
        else                 { CP_WAIT0(); }
        __syncthreads();

        const uint32_t* pAh = reinterpret_cast<const uint32_t*>(smem + (c % 3) * ST_BYTES);
        const uint32_t* pAl = pAh + 128*AW;
        const uint32_t* pBh = pAh + 2*128*AW;
        const uint32_t* pBl = pBh + 16*BW;

#pragma unroll
        for (int ks = 0; ks < 2; ks++) {
            const int kb = ks * 8;
            uint32_t Ah[4][4], Al[4][4];
#pragma unroll
            for (int mt = 0; mt < 4; mt++) {
                const int r0 = wy*64 + mt*16 + gid;
                Ah[mt][0] = pAh[(r0    )*AW + kb + tig    ];
                Ah[mt][1] = pAh[(r0 + 8)*AW + kb + tig    ];
                Ah[mt][2] = pAh[(r0    )*AW + kb + tig + 4];
                Ah[mt][3] = pAh[(r0 + 8)*AW + kb + tig + 4];
                Al[mt][0] = pAl[(r0    )*AW + kb + tig    ];
                Al[mt][1] = pAl[(r0 + 8)*AW + kb + tig    ];
                Al[mt][2] = pAl[(r0    )*AW + kb + tig + 4];
                Al[mt][3] = pAl[(r0 + 8)*AW + kb + tig + 4];
            }
#pragma unroll
            for (int nt = 0; nt < 8; nt++) {
                const int col = wx*64 + nt*8 + gid;
                uint32_t bh0 = pBh[(kb + tig    )*BW + col];
                uint32_t bh1 = pBh[(kb + tig + 4)*BW + col];
                uint32_t bl0 = pBl[(kb + tig    )*BW + col];
                uint32_t bl1 = pBl[(kb + tig + 4)*BW + col];
#pragma unroll
                for (int mt = 0; mt < 4; mt++) {
                    MMA_BF16(acc[mt][nt], Ah[mt][0], Ah[mt][1], Ah[mt][2], Ah[mt][3],
                             bh0, bh1);
                    MMA_BF16(acc[mt][nt], Al[mt][0], Al[mt][1], Al[mt][2], Al[mt][3],
                             bh0, bh1);
                    MMA_BF16(acc[mt][nt], Ah[mt][0], Ah[mt][1], Ah[mt][2], Ah[mt][3],
                             bl0, bl1);
                }
            }
        }
        __syncthreads();
    }

    // epilogue
    const int Np = N >> 1;
#pragma unroll
    for (int nt = 0; nt < 8; nt++) {
        const int cc = bn + wx*64 + nt*8 + tig*2;
        const float b0 = bias[cc], b1 = bias[cc + 1];
#pragma unroll
        for (int mt = 0; mt < 4; mt++) {
            const int r0 = bm + wy*64 + mt*16 + gid;
            float v0 = acc[mt][nt][0] + b0;
            float v1 = acc[mt][nt][1] + b1;
            float v2 = acc[mt][nt][2] + b0;
            float v3 = acc[mt][nt][3] + b1;
            if (RELU) {
                v0 = fmaxf(v0, 0.f); v1 = fmaxf(v1, 0.f);
                v2 = fmaxf(v2, 0.f); v3 = fmaxf(v3, 0.f);
            }
            if (PACK_OUT) {
                uint32_t h, l;
                split_pack(v0, v1, h, l);
                Ohi[(size_t)r0 * Np + (cc >> 1)] = h;
                Olo[(size_t)r0 * Np + (cc >> 1)] = l;
                split_pack(v2, v3, h, l);
                Ohi[(size_t)(r0 + 8) * Np + (cc >> 1)] = h;
                Olo[(size_t)(r0 + 8) * Np + (cc >> 1)] = l;
            } else {
                *reinterpret_cast<float2*>(C + (size_t)r0 * N + cc)       = make_float2(v0, v1);
                *reinterpret_cast<float2*>(C + (size_t)(r0 + 8) * N + cc) = make_float2(v2, v3);
            }
        }
    }
#undef ISSUE
}

// ======================= fused flash attention (bf16x3) ====================
// One CTA per (bh, 128-row q tile). 256 threads, 8 warps.
// Q,K pre-split packed along dk; V transpose-packed in-kernel; P packed from
// MMA accumulators during register softmax.
#define QW   36   // u32 stride for Q/K packed rows (32 + 4)
#define VtW  65   // u32 stride for Vt rows (64 + 1)
#define PsW  66   // u32 stride for P rows (64 + 2)
#define FQH  0
#define FQL  (FQH + 128*QW*4)        // 18432
#define FKH  (FQL + 128*QW*4)        // 36864
#define FKL  (FKH + 128*QW*4)        // 55296
#define FVH  (FKL + 128*QW*4)        // 73728
#define FVL  (FVH + 64*VtW*4)        // 90368
#define FPH  (FVL + 64*VtW*4)        // 107008
#define FPL  (FPH + 128*PsW*4)       // 140800
#define FMS  (FPL + 128*PsW*4)       // 174592
#define FLS  (FMS + 128*4)
#define FALS (FLS + 128*4)
#define FRED (FALS + 128*4)
#define FA_SMEM (FRED + 4*128*4)     // 178176

__global__ __launch_bounds__(256, 1) void flash_attn_kernel(
    const uint32_t* __restrict__ qh_g, const uint32_t* __restrict__ ql_g,
    const uint32_t* __restrict__ kh_g, const uint32_t* __restrict__ kl_g,
    const float* __restrict__ v, float* __restrict__ ctx)
{
    extern __shared__ char smem[];
    uint32_t* QsH = reinterpret_cast<uint32_t*>(smem + FQH);
    uint32_t* QsL = reinterpret_cast<uint32_t*>(smem + FQL);
    uint32_t* KsH = reinterpret_cast<uint32_t*>(smem + FKH);
    uint32_t* KsL = reinterpret_cast<uint32_t*>(smem + FKL);
    uint32_t* VtH = reinterpret_cast<uint32_t*>(smem + FVH);
    uint32_t* VtL = reinterpret_cast<uint32_t*>(smem + FVL);
    uint32_t* PsH = reinterpret_cast<uint32_t*>(smem + FPH);
    uint32_t* PsL = reinterpret_cast<uint32_t*>(smem + FPL);
    float* m_s  = reinterpret_cast<float*>(smem + FMS);
    float* l_s  = reinterpret_cast<float*>(smem + FLS);
    float* al_s = reinterpret_cast<float*>(smem + FALS);
    float* red  = reinterpret_cast<float*>(smem + FRED);

    const int tid = threadIdx.x;
    const int wid = tid >> 5;
    const int lane = tid & 31;
    const int gid = lane >> 2;
    const int tig = lane & 3;

    const int bh = blockIdx.x;
    const int b  = bh >> 4, h = bh & 15;
    const int q0 = blockIdx.y * 128;

    // load Q packed tile [128 x 32 words]
    {
        const uint32_t* qh = qh_g + (size_t)(b*SEQ + q0) * (D_MODEL/2) + h*32;
        const uint32_t* ql = ql_g + (size_t)(b*SEQ + q0) * (D_MODEL/2) + h*32;
#pragma unroll
        for (int i = 0; i < 4; i++) {
            int idx = tid + i * 256;
            int row = idx >> 3, qq = idx & 7;
            *reinterpret_cast<uint4*>(QsH + row*QW + qq*4) =
                *reinterpret_cast<const uint4*>(qh + (size_t)row * (D_MODEL/2) + qq*4);
            *reinterpret_cast<uint4*>(QsL + row*QW + qq*4) =
                *reinterpret_cast<const uint4*>(ql + (size_t)row * (D_MODEL/2) + qq*4);
        }
    }
    if (tid < 128) { m_s[tid] = -INFINITY; l_s[tid] = 0.f; }

    // O accumulators: warp tile 32x32 over 128x64
    const int wy2 = wid >> 1;      // 0..3
    const int wx2 = wid & 1;       // 0..1
    float acc_o[2][4][4];
#pragma unroll
    for (int mt = 0; mt < 2; mt++)
#pragma unroll
        for (int nt = 0; nt < 4; nt++)
#pragma unroll
            for (int r = 0; r < 4; r++) acc_o[mt][nt][r] = 0.f;

    // S warp tile 64x32 over 128x128
    const int wy = wid >> 2;       // 0..1
    const int wx = wid & 3;        // 0..3

    for (int kt = 0; kt < 4; kt++) {
        __syncthreads();
        const int s0 = kt * 128;
        // K packed tile
        {
            const uint32_t* kh = kh_g + (size_t)(b*SEQ + s0) * (D_MODEL/2) + h*32;
            const uint32_t* kl = kl_g + (size_t)(b*SEQ + s0) * (D_MODEL/2) + h*32;
#pragma unroll
            for (int i = 0; i < 4; i++) {
                int idx = tid + i * 256;
                int row = idx >> 3, qq = idx & 7;
                *reinterpret_cast<uint4*>(KsH + row*QW + qq*4) =
                    *reinterpret_cast<const uint4*>(kh + (size_t)row * (D_MODEL/2) + qq*4);
                *reinterpret_cast<uint4*>(KsL + row*QW + qq*4) =
                    *reinterpret_cast<const uint4*>(kl + (size_t)row * (D_MODEL/2) + qq*4);
            }
        }
        // V transpose-pack: Vt[dk][sp] = pack(V[2sp][dk], V[2sp+1][dk])
        {
            const float* vg = v + (size_t)(b*SEQ + s0) * D_MODEL + h*DK;
#pragma unroll
            for (int i = 0; i < 4; i++) {
                int idx = tid + i * 256;
                int sp = idx >> 4, dk4 = idx & 15;
                float4 r0v = *reinterpret_cast<const float4*>(vg + (size_t)(2*sp  ) * D_MODEL + dk4*4);
                float4 r1v = *reinterpret_cast<const float4*>(vg + (size_t)(2*sp+1) * D_MODEL + dk4*4);
                uint32_t hh, ll;
                split_pack(r0v.x, r1v.x, hh, ll);
                VtH[(dk4*4+0)*VtW + sp] = hh; VtL[(dk4*4+0)*VtW + sp] = ll;
                split_pack(r0v.y, r1v.y, hh, ll);
                VtH[(dk4*4+1)*VtW + sp] = hh; VtL[(dk4*4+1)*VtW + sp] = ll;
                split_pack(r0v.z, r1v.z, hh, ll);
                VtH[(dk4*4+2)*VtW + sp] = hh; VtL[(dk4*4+2)*VtW + sp] = ll;
                split_pack(r0v.w, r1v.w, hh, ll);
                VtH[(dk4*4+3)*VtW + sp] = hh; VtL[(dk4*4+3)*VtW + sp] = ll;
            }
        }
        __syncthreads();

        // ---- S = Q @ K^T (128x128, k=64 -> 4 k16 steps) ----
        float s_acc[4][4][4];
#pragma unroll
        for (int i = 0; i < 4; i++)
#pragma unroll
            for (int j = 0; j < 4; j++)
#pragma unroll
                for (int r = 0; r < 4; r++) s_acc[i][j][r] = 0.f;

#pragma unroll
        for (int ks = 0; ks < 4; ks++) {
            const int kb = ks * 8;
            uint32_t Ah[4][4], Al[4][4];
#pragma unroll
            for (int mt = 0; mt < 4; mt++) {
                const int r0 = wy*64 + mt*16 + gid;
                Ah[mt][0] = QsH[(r0    )*QW + kb + tig    ];
                Ah[mt][1] = QsH[(r0 + 8)*QW + kb + tig    ];
                Ah[mt][2] = QsH[(r0    )*QW + kb + tig + 4];
                Ah[mt][3] = QsH[(r0 + 8)*QW + kb + tig + 4];
                Al[mt][0] = QsL[(r0    )*QW + kb + tig    ];
                Al[mt][1] = QsL[(r0 + 8)*QW + kb + tig    ];
                Al[mt][2] = QsL[(r0    )*QW + kb + tig + 4];
                Al[mt][3] = QsL[(r0 + 8)*QW + kb + tig + 4];
            }
#pragma unroll
            for (int nt = 0; nt < 4; nt++) {
                const int col = wx*32 + nt*8 + gid;
                uint32_t bh0 = KsH[col*QW + kb + tig    ];
                uint32_t bh1 = KsH[col*QW + kb + tig + 4];
                uint32_t bl0 = KsL[col*QW + kb + tig    ];
                uint32_t bl1 = KsL[col*QW + kb + tig + 4];
#pragma unroll
                for (int mt = 0; mt < 4; mt++) {
                    MMA_BF16(s_acc[mt][nt], Ah[mt][0], Ah[mt][1], Ah[mt][2], Ah[mt][3],
                             bh0, bh1);
                    MMA_BF16(s_acc[mt][nt], Al[mt][0], Al[mt][1], Al[mt][2], Al[mt][3],
                             bh0, bh1);
                    MMA_BF16(s_acc[mt][nt], Ah[mt][0], Ah[mt][1], Ah[mt][2], Ah[mt][3],
                             bl0, bl1);
                }
            }
        }

        // scale + per-warp row max
#pragma unroll
        for (int mt = 0; mt < 4; mt++) {
            float rlo = -INFINITY, rhi = -INFINITY;
#pragma unroll
            for (int nt = 0; nt < 4; nt++) {
                s_acc[mt][nt][0] *= 0.125f; s_acc[mt][nt][1] *= 0.125f;
                s_acc[mt][nt][2] *= 0.125f; s_acc[mt][nt][3] *= 0.125f;
                rlo = fmaxf(rlo, fmaxf(s_acc[mt][nt][0], s_acc[mt][nt][1]));
                rhi = fmaxf(rhi, fmaxf(s_acc[mt][nt][2], s_acc[mt][nt][3]));
            }
            rlo = fmaxf(rlo, __shfl_xor_sync(~0u, rlo, 1));
            rlo = fmaxf(rlo, __shfl_xor_sync(~0u, rlo, 2));
            rhi = fmaxf(rhi, __shfl_xor_sync(~0u, rhi, 1));
            rhi = fmaxf(rhi, __shfl_xor_sync(~0u, rhi, 2));
            if (tig == 0) {
                const int r0 = wy*64 + mt*16 + gid;
                red[wx*128 + r0]     = rlo;
                red[wx*128 + r0 + 8] = rhi;
            }
        }
        __syncthreads();
        if (tid < 128) {
            float mo = m_s[tid];
            float mn = fmaxf(fmaxf(red[tid], red[128 + tid]),
                             fmaxf(red[256 + tid], red[384 + tid]));
            mn = fmaxf(mo, mn);
            al_s[tid] = __expf(mo - mn);
            m_s[tid]  = mn;
        }
        __syncthreads();

        // exp + pack P + partial row sums
#pragma unroll
        for (int mt = 0; mt < 4; mt++) {
            const int rlo = wy*64 + mt*16 + gid;
            const float mlo = m_s[rlo];
            const float mhi = m_s[rlo + 8];
            float slo = 0.f, shi = 0.f;
#pragma unroll
            for (int nt = 0; nt < 4; nt++) {
                float d0 = __expf(s_acc[mt][nt][0] - mlo);
                float d1 = __expf(s_acc[mt][nt][1] - mlo);
                float d2 = __expf(s_acc[mt][nt][2] - mhi);
                float d3 = __expf(s_acc[mt][nt][3] - mhi);
                slo += d0 + d1; shi += d2 + d3;
                const int word = wx*16 + nt*4 + tig;
                uint32_t hh, ll;
                split_pack(d0, d1, hh, ll);
                PsH[rlo*PsW + word] = hh; PsL[rlo*PsW + word] = ll;
                split_pack(d2, d3, hh, ll);
                PsH[(rlo+8)*PsW + word] = hh; PsL[(rlo+8)*PsW + word] = ll;
            }
            slo += __shfl_xor_sync(~0u, slo, 1);
            slo += __shfl_xor_sync(~0u, slo, 2);
            shi += __shfl_xor_sync(~0u, shi, 1);
            shi += __shfl_xor_sync(~0u, shi, 2);
            if (tig == 0) {
                red[wx*128 + rlo]     = slo;
                red[wx*128 + rlo + 8] = shi;
            }
        }
        // rescale O by alpha
#pragma unroll
        for (int mt = 0; mt < 2; mt++) {
            const int r0 = wy2*32 + mt*16 + gid;
            const float aL = al_s[r0];
            const float aH = al_s[r0 + 8];
#pragma unroll
            for (int nt = 0; nt < 4; nt++) {
                acc_o[mt][nt][0] *= aL; acc_o[mt][nt][1] *= aL;
                acc_o[mt][nt][2] *= aH; acc_o[mt][nt][3] *= aH;
            }
        }
        __syncthreads();
        if (tid < 128) {
            l_s[tid] = al_s[tid] * l_s[tid] +
                       (red[tid] + red[128 + tid] + red[256 + tid] + red[384 + tid]);
        }

        // ---- O += P @ V  (128x64, k=128 -> 8 k16 steps) ----
#pragma unroll
        for (int ks = 0; ks < 8; ks++) {
            const int kb = ks * 8;
            uint32_t Ph[2][4], Pl[2][4];
#pragma unroll
            for (int mt = 0; mt < 2; mt++) {
                const int r0 = wy2*32 + mt*16 + gid;
                Ph[mt][0] = PsH[(r0    )*PsW + kb + tig    ];
                Ph[mt][1] = PsH[(r0 + 8)*PsW + kb + tig    ];
                Ph[mt][2] = PsH[(r0    )*PsW + kb + tig + 4];
                Ph[mt][3] = PsH[(r0 + 8)*PsW + kb + tig + 4];
                Pl[mt][0] = PsL[(r0    )*PsW + kb + tig    ];
                Pl[mt][1] = PsL[(r0 + 8)*PsW + kb + tig    ];
                Pl[mt][2] = PsL[(r0    )*PsW + kb + tig + 4];
                Pl[mt][3] = PsL[(r0 + 8)*PsW + kb + tig + 4];
            }
#pragma unroll
            for (int nt = 0; nt < 4; nt++) {
                const int dc = wx2*32 + nt*8 + gid;
                uint32_t vh0 = VtH[dc*VtW + kb + tig    ];
                uint32_t vh1 = VtH[dc*VtW + kb + tig + 4];
                uint32_t vl0 = VtL[dc*VtW + kb + tig    ];
                uint32_t vl1 = VtL[dc*VtW + kb + tig + 4];
#pragma unroll
                for (int mt = 0; mt < 2; mt++) {
                    MMA_BF16(acc_o[mt][nt], Ph[mt][0], Ph[mt][1], Ph[mt][2], Ph[mt][3],
                             vh0, vh1);
                    MMA_BF16(acc_o[mt][nt], Pl[mt][0], Pl[mt][1], Pl[mt][2], Pl[mt][3],
                             vh0, vh1);
                    MMA_BF16(acc_o[mt][nt], Ph[mt][0], Ph[mt][1], Ph[mt][2], Ph[mt][3],
                             vl0, vl1);
                }
            }
        }
    }

    __syncthreads();
#pragma unroll
    for (int mt = 0; mt < 2; mt++) {
        const int r0 = wy2*32 + mt*16 + gid;
        const float iL = 1.f / l_s[r0];
        const float iH = 1.f / l_s[r0 + 8];
#pragma unroll
        for (int nt = 0; nt < 4; nt++) {
            const int dc = h*DK + wx2*32 + nt*8 + tig*2;
            const size_t rowL = (size_t)(b*SEQ + q0 + r0);
            *reinterpret_cast<float2*>(ctx + rowL * D_MODEL + dc) =
                make_float2(acc_o[mt][nt][0]*iL, acc_o[mt][nt][1]*iL);
            *reinterpret_cast<float2*>(ctx + (rowL+8) * D_MODEL + dc) =
                make_float2(acc_o[mt][nt][2]*iH, acc_o[mt][nt][3]*iH);
        }
    }
}

// ---------------- fused residual-add + LayerNorm (+ optional bf16 packing) ---
template<bool PACK>
__global__ __launch_bounds__(256) void add_ln_kernel(
    const float* __restrict__ a, const float* __restrict__ r,
    const float* __restrict__ g, const float* __restrict__ be,
    float* __restrict__ out, uint32_t* __restrict__ Ohi,
    uint32_t* __restrict__ Olo)
{
    __shared__ float reds[8], reds2[8];
    __shared__ float s_mean, s_inv;
    const int row = blockIdx.x;
    const int tid = threadIdx.x;
    const int c0 = tid * 4;
    float4 va = *reinterpret_cast<const float4*>(a + (size_t)row * D_MODEL + c0);
    float4 vr = *reinterpret_cast<const float4*>(r + (size_t)row * D_MODEL + c0);
    float v0 = va.x + vr.x, v1 = va.y + vr.y, v2 = va.z + vr.z, v3 = va.w + vr.w;
    float s  = v0 + v1 + v2 + v3;
    float s2 = v0*v0 + v1*v1 + v2*v2 + v3*v3;
#pragma unroll
    for (int o = 16; o > 0; o >>= 1) {
        s  += __shfl_xor_sync(~0u, s,  o);
        s2 += __shfl_xor_sync(~0u, s2, o);
    }
    if ((tid & 31) == 0) { reds[tid >> 5] = s; reds2[tid >> 5] = s2; }
    __syncthreads();
    if (tid < 32) {
        float v  = (tid < 8) ? reds[tid]  : 0.f;
        float vv = (tid < 8) ? reds2[tid] : 0.f;
#pragma unroll
        for (int o = 4; o > 0; o >>= 1) {
            v  += __shfl_xor_sync(~0u, v,  o);
            vv += __shfl_xor_sync(~0u, vv, o);
        }
        if (tid == 0) {
            float mean = v * (1.f / D_MODEL);
            float var  = vv * (1.f / D_MODEL) - mean * mean;
            s_mean = mean;
            s_inv  = rsqrtf(var + 1e-5f);
        }
    }
    __syncthreads();
    const float mean = s_mean, inv = s_inv;
    float4 gg = *reinterpret_cast<const float4*>(g  + c0);
    float4 bb = *reinterpret_cast<const float4*>(be + c0);
    float o0 = (v0 - mean) * inv * gg.x + bb.x;
    float o1 = (v1 - mean) * inv * gg.y + bb.y;
    float o2 = (v2 - mean) * inv * gg.z + bb.z;
    float o3 = (v3 - mean) * inv * gg.w + bb.w;
    *reinterpret_cast<float4*>(out + (size_t)row * D_MODEL + c0) =
        make_float4(o0, o1, o2, o3);
    if (PACK) {
        uint32_t h0, l0, h1, l1;
        split_pack(o0, o1, h0, l0);
        split_pack(o2, o3, h1, l1);
        *reinterpret_cast<uint2*>(Ohi + (size_t)row * (D_MODEL/2) + tid*2) = make_uint2(h0, h1);
        *reinterpret_cast<uint2*>(Olo + (size_t)row * (D_MODEL/2) + tid*2) = make_uint2(l0, l1);
    }
}

// ---------------- launch -----------------------------------------------------
extern "C" void kernel_launch(void* const* d_in, const int* in_sizes, int n_in,
                              void* d_out, int out_size)
{
    const float* src = (const float*)d_in[0];
    const float* wq  = (const float*)d_in[1];
    const float* bq  = (const float*)d_in[2];
    const float* wk  = (const float*)d_in[3];
    const float* bk  = (const float*)d_in[4];
    const float* wv  = (const float*)d_in[5];
    const float* bv  = (const float*)d_in[6];
    const float* g1  = (const float*)d_in[7];
    const float* be1 = (const float*)d_in[8];
    const float* w1  = (const float*)d_in[9];
    const float* b1  = (const float*)d_in[10];
    const float* w2  = (const float*)d_in[11];
    const float* b2  = (const float*)d_in[12];
    const float* g2  = (const float*)d_in[13];
    const float* be2 = (const float*)d_in[14];
    float* out = (float*)d_out;

    float *pv, *pctx, *px, *py;
    uint32_t *srcp_hi, *srcp_lo, *qp_hi, *qp_lo, *kp_hi, *kp_lo;
    uint32_t *xp_hi, *xp_lo, *hp_hi, *hp_lo;
    uint32_t *wqp_hi, *wqp_lo, *wkp_hi, *wkp_lo, *wvp_hi, *wvp_lo;
    uint32_t *w1p_hi, *w1p_lo, *w2p_hi, *w2p_lo;
    cudaGetSymbolAddress((void**)&pv,   g_v);
    cudaGetSymbolAddress((void**)&pctx, g_ctx);
    cudaGetSymbolAddress((void**)&px,   g_x);
    cudaGetSymbolAddress((void**)&py,   g_y);
    cudaGetSymbolAddress((void**)&srcp_hi, g_srcp_hi);
    cudaGetSymbolAddress((void**)&srcp_lo, g_srcp_lo);
    cudaGetSymbolAddress((void**)&qp_hi,   g_qp_hi);
    cudaGetSymbolAddress((void**)&qp_lo,   g_qp_lo);
    cudaGetSymbolAddress((void**)&kp_hi,   g_kp_hi);
    cudaGetSymbolAddress((void**)&kp_lo,   g_kp_lo);
    cudaGetSymbolAddress((void**)&xp_hi,   g_xp_hi);
    cudaGetSymbolAddress((void**)&xp_lo,   g_xp_lo);
    cudaGetSymbolAddress((void**)&hp_hi,   g_hp_hi);
    cudaGetSymbolAddress((void**)&hp_lo,   g_hp_lo);
    cudaGetSymbolAddress((void**)&wqp_hi,  g_wqp_hi);
    cudaGetSymbolAddress((void**)&wqp_lo,  g_wqp_lo);
    cudaGetSymbolAddress((void**)&wkp_hi,  g_wkp_hi);
    cudaGetSymbolAddress((void**)&wkp_lo,  g_wkp_lo);
    cudaGetSymbolAddress((void**)&wvp_hi,  g_wvp_hi);
    cudaGetSymbolAddress((void**)&wvp_lo,  g_wvp_lo);
    cudaGetSymbolAddress((void**)&w1p_hi,  g_w1p_hi);
    cudaGetSymbolAddress((void**)&w1p_lo,  g_w1p_lo);
    cudaGetSymbolAddress((void**)&w2p_hi,  g_w2p_hi);
    cudaGetSymbolAddress((void**)&w2p_lo,  g_w2p_lo);

    cudaFuncSetAttribute(gemm_bf16_kernel<false,false>,
                         cudaFuncAttributeMaxDynamicSharedMemorySize, GEMM_SMEM);
    cudaFuncSetAttribute(gemm_bf16_kernel<false,true>,
                         cudaFuncAttributeMaxDynamicSharedMemorySize, GEMM_SMEM);
    cudaFuncSetAttribute(gemm_bf16_kernel<true,true>,
                         cudaFuncAttributeMaxDynamicSharedMemorySize, GEMM_SMEM);
    cudaFuncSetAttribute(flash_attn_kernel,
                         cudaFuncAttributeMaxDynamicSharedMemorySize, FA_SMEM);

    // pack inputs
    pack_act_kernel<<<TOKENS*D_MODEL/4/256, 256>>>(src, srcp_hi, srcp_lo,
                                                   TOKENS*D_MODEL/4);
    pack_weight_kernel<<<(D_MODEL/2)*(D_MODEL/4)/256, 256>>>(wq, wqp_hi, wqp_lo,
                                                             D_MODEL/2, D_MODEL);
    pack_weight_kernel<<<(D_MODEL/2)*(D_MODEL/4)/256, 256>>>(wk, wkp_hi, wkp_lo,
                                                             D_MODEL/2, D_MODEL);
    pack_weight_kernel<<<(D_MODEL/2)*(D_MODEL/4)/256, 256>>>(wv, wvp_hi, wvp_lo,
                                                             D_MODEL/2, D_MODEL);
    pack_weight_kernel<<<(D_MODEL/2)*(FEED/4)/256, 256>>>(w1, w1p_hi, w1p_lo,
                                                          D_MODEL/2, FEED);
    pack_weight_kernel<<<(FEED/2)*(D_MODEL/4)/256, 256>>>(w2, w2p_hi, w2p_lo,
                                                          FEED/2, D_MODEL);

    // QKV projections: Q,K emit packed bf16; V emits fp32
    gemm_bf16_kernel<false,true><<<dim3(D_MODEL/256, TOKENS/128), 256, GEMM_SMEM>>>(
        srcp_hi, srcp_lo, wqp_hi, wqp_lo, bq, nullptr, qp_hi, qp_lo,
        TOKENS, D_MODEL, D_MODEL);
    gemm_bf16_kernel<false,true><<<dim3(D_MODEL/256, TOKENS/128), 256, GEMM_SMEM>>>(
        srcp_hi, srcp_lo, wkp_hi, wkp_lo, bk, nullptr, kp_hi, kp_lo,
        TOKENS, D_MODEL, D_MODEL);
    gemm_bf16_kernel<false,false><<<dim3(D_MODEL/256, TOKENS/128), 256, GEMM_SMEM>>>(
        srcp_hi, srcp_lo, wvp_hi, wvp_lo, bv, pv, nullptr, nullptr,
        TOKENS, D_MODEL, D_MODEL);

    // fused flash attention (bf16x3)
    flash_attn_kernel<<<dim3(BH, SEQ/128), 256, FA_SMEM>>>(
        qp_hi, qp_lo, kp_hi, kp_lo, pv, pctx);

    // residual + LN1 (emit packed x for FFN1)
    add_ln_kernel<true><<<TOKENS, 256>>>(pctx, src, g1, be1, px, xp_hi, xp_lo);

    // FFN1: relu, packed output only
    gemm_bf16_kernel<true,true><<<dim3(FEED/256, TOKENS/128), 256, GEMM_SMEM>>>(
        xp_hi, xp_lo, w1p_hi, w1p_lo, b1, nullptr, hp_hi, hp_lo,
        TOKENS, FEED, D_MODEL);
    // FFN2
    gemm_bf16_kernel<false,false><<<dim3(D_MODEL/256, TOKENS/128), 256, GEMM_SMEM>>>(
        hp_hi, hp_lo, w2p_hi, w2p_lo, b2, py, nullptr, nullptr,
        TOKENS, D_MODEL, FEED);

    // residual + LN2 -> output
    add_ln_kernel<false><<<TOKENS, 256>>>(py, px, g2, be2, out, nullptr, nullptr);
}